// round 6
// baseline (speedup 1.0000x reference)
#include <cuda_runtime.h>
#include <math.h>

// ---------------- problem constants ----------------
#define B_       2
#define S_       2048
#define DIM_     2048
#define NH_      16
#define QKD_     192     // NOPE(128) + ROPE(64)
#define NOPE_    128
#define ROPE_    64
#define VD_      128
#define KVLORA_  512
#define NTOK_    (B_ * S_)   // 4096

// ---------------- scratch (static device globals; no allocation) ----------------
__device__ float g_q   [NTOK_ * (NH_ * QKD_)];          // 4096 x 3072
__device__ float g_kv  [NTOK_ * (KVLORA_ + ROPE_)];     // 4096 x 576
__device__ float g_kvc [NTOK_ * KVLORA_];               // 4096 x 512
__device__ float g_kpe [NTOK_ * ROPE_];                 // 4096 x 64
__device__ float g_kvb [NTOK_ * (NH_ * (NOPE_ + VD_))]; // 4096 x 4096
__device__ float g_attn[NTOK_ * (NH_ * VD_)];           // 4096 x 2048

// ============================================================================
// Generic SGEMM:  C[M,N] = A[M,K] * B[N,K]^T   (both row-major, K contiguous)
// 128x128 tile, BK=8, 256 threads, 8x8 register micro-tile.
// Requires K % 8 == 0, M % 128 == 0 (true for all calls); N guarded.
// ============================================================================
__global__ __launch_bounds__(256) void sgemm_nt(
    const float* __restrict__ A, const float* __restrict__ B,
    float* __restrict__ C, int M, int N, int K)
{
    __shared__ float As[8][128];
    __shared__ float Bs[8][128];

    const int bm  = blockIdx.y * 128;
    const int bn  = blockIdx.x * 128;
    const int tid = threadIdx.x;
    const int tx  = tid & 15;
    const int ty  = tid >> 4;

    // loader mapping: each thread loads one float4 of A and one of B per BK step
    const int lrow = tid >> 1;        // 0..127
    const int lseg = (tid & 1) * 4;   // 0 or 4

    float acc[8][8];
#pragma unroll
    for (int i = 0; i < 8; i++)
#pragma unroll
        for (int j = 0; j < 8; j++) acc[i][j] = 0.f;

    for (int k0 = 0; k0 < K; k0 += 8) {
        // load A tile (transposed into As[k][m])
        {
            const int gm = bm + lrow;
            float4 v = make_float4(0.f, 0.f, 0.f, 0.f);
            if (gm < M) v = *(const float4*)(A + (size_t)gm * K + k0 + lseg);
            As[lseg + 0][lrow] = v.x; As[lseg + 1][lrow] = v.y;
            As[lseg + 2][lrow] = v.z; As[lseg + 3][lrow] = v.w;

            const int gn = bn + lrow;
            float4 w = make_float4(0.f, 0.f, 0.f, 0.f);
            if (gn < N) w = *(const float4*)(B + (size_t)gn * K + k0 + lseg);
            Bs[lseg + 0][lrow] = w.x; Bs[lseg + 1][lrow] = w.y;
            Bs[lseg + 2][lrow] = w.z; Bs[lseg + 3][lrow] = w.w;
        }
        __syncthreads();

#pragma unroll
        for (int k = 0; k < 8; k++) {
            float4 a0 = *(const float4*)&As[k][ty * 8];
            float4 a1 = *(const float4*)&As[k][ty * 8 + 4];
            float4 b0 = *(const float4*)&Bs[k][tx * 8];
            float4 b1 = *(const float4*)&Bs[k][tx * 8 + 4];
            float a[8] = {a0.x, a0.y, a0.z, a0.w, a1.x, a1.y, a1.z, a1.w};
            float b[8] = {b0.x, b0.y, b0.z, b0.w, b1.x, b1.y, b1.z, b1.w};
#pragma unroll
            for (int i = 0; i < 8; i++)
#pragma unroll
                for (int j = 0; j < 8; j++) acc[i][j] = fmaf(a[i], b[j], acc[i][j]);
        }
        __syncthreads();
    }

#pragma unroll
    for (int i = 0; i < 8; i++) {
        const int gm = bm + ty * 8 + i;
        if (gm >= M) continue;
#pragma unroll
        for (int j = 0; j < 8; j++) {
            const int gn = bn + tx * 8 + j;
            if (gn < N) C[(size_t)gm * N + gn] = acc[i][j];
        }
    }
}

// ============================================================================
// NOTE: the reference applies RoPE only to k_pe. It computes a rotated q_pe
// copy but the score einsum uses the ORIGINAL (un-rotated) q, so there is
// deliberately NO q-RoPE kernel here.
// ============================================================================

// ============================================================================
// Per-token: RMSNorm(kv_c) -> g_kvc ; RoPE(k_pe) -> g_kpe.
// One block (128 threads) per token.
// ============================================================================
__global__ __launch_bounds__(128) void kv_post_kernel(
    const float* __restrict__ kv, const float* __restrict__ kvnw,
    const float* __restrict__ fc, const float* __restrict__ fs,
    float* __restrict__ kvc, float* __restrict__ kpe)
{
    const int tok = blockIdx.x;
    const int s   = tok & (S_ - 1);
    const float* row = kv + (size_t)tok * (KVLORA_ + ROPE_);

    __shared__ float red[4];
    float ss = 0.f;
    for (int d = threadIdx.x; d < KVLORA_; d += 128) {
        const float v = row[d];
        ss += v * v;
    }
#pragma unroll
    for (int off = 16; off; off >>= 1) ss += __shfl_xor_sync(0xffffffffu, ss, off);
    if ((threadIdx.x & 31) == 0) red[threadIdx.x >> 5] = ss;
    __syncthreads();
    const float tot = red[0] + red[1] + red[2] + red[3];
    const float rn  = rsqrtf(tot / (float)KVLORA_ + 1e-6f);

    for (int d = threadIdx.x; d < KVLORA_; d += 128)
        kvc[(size_t)tok * KVLORA_ + d] = row[d] * rn * kvnw[d];

    if (threadIdx.x < 32) {
        const int p  = threadIdx.x;
        const float xr = row[KVLORA_ + 2 * p];
        const float xi = row[KVLORA_ + 2 * p + 1];
        const float c  = fc[s * 32 + p];
        const float sn = fs[s * 32 + p];
        kpe[(size_t)tok * ROPE_ + 2 * p]     = xr * c - xi * sn;
        kpe[(size_t)tok * ROPE_ + 2 * p + 1] = xr * sn + xi * c;
    }
}

// ============================================================================
// Causal flash attention (fp32 SIMT).
// grid = (S/64, NH, B), 256 threads (16x16), 4x4 score micro-tile,
// 4x8 output micro-tile. Q tile resident in SMEM; K (transposed), V, P staged.
// ============================================================================
#define BM_ 64
#define BN_ 64
#define KSP 68   // padded width for Ks rows / Ps rows
#define VSP 132  // padded width for Vs rows

// SMEM floats: Qs 64*192 + Ks 192*68 + Vs 64*132 + Ps 64*68
#define FA_SMEM_FLOATS (BM_*QKD_ + QKD_*KSP + BN_*VSP + BM_*KSP)
#define FA_SMEM_BYTES  (FA_SMEM_FLOATS * 4)

__global__ __launch_bounds__(256) void flash_attn_kernel(
    const float* __restrict__ q,    // (tok, head, 192)  -- UN-rotated, per reference
    const float* __restrict__ kvb,  // (tok, head, 256)  [k_nope | v]
    const float* __restrict__ kpe,  // (tok, 64)         -- rotated
    float* __restrict__ o,          // (tok, head, 128)
    float scale)
{
    extern __shared__ float sm[];
    float* Qs = sm;                         // [64][192] row-major
    float* Ks = Qs + BM_ * QKD_;            // [192][68] transposed
    float* Vs = Ks + QKD_ * KSP;            // [64][132] row-major
    float* Ps = Vs + BN_ * VSP;             // [64][68]

    const int qb  = blockIdx.x;
    const int h   = blockIdx.y;
    const int b   = blockIdx.z;
    const int tid = threadIdx.x;
    const int tx  = tid & 15;
    const int ty  = tid >> 4;

    const size_t tok0 = (size_t)b * S_ + (size_t)qb * BM_;

    // load Q tile (coalesced along d)
    for (int idx = tid; idx < BM_ * QKD_; idx += 256) {
        const int m = idx / QKD_, d = idx - m * QKD_;
        Qs[m * QKD_ + d] = q[((tok0 + m) * NH_ + h) * QKD_ + d];
    }

    float m_i[4], l_i[4], oacc[4][8];
#pragma unroll
    for (int i = 0; i < 4; i++) {
        m_i[i] = -1e30f; l_i[i] = 0.f;
#pragma unroll
        for (int j = 0; j < 8; j++) oacc[i][j] = 0.f;
    }
    __syncthreads();

    for (int kb = 0; kb <= qb; kb++) {
        const size_t ktok0 = (size_t)b * S_ + (size_t)kb * BN_;

        // stage K tile transposed: Ks[d][n]
        for (int idx = tid; idx < BN_ * QKD_; idx += 256) {
            const int n = idx / QKD_, d = idx - n * QKD_;
            float v;
            if (d < NOPE_) v = kvb[((ktok0 + n) * NH_ + h) * (NOPE_ + VD_) + d];
            else           v = kpe[(ktok0 + n) * ROPE_ + (d - NOPE_)];
            Ks[d * KSP + n] = v;
        }
        // stage V tile: Vs[n][d]
        for (int idx = tid; idx < BN_ * VD_; idx += 256) {
            const int n = idx >> 7, d = idx & 127;
            Vs[n * VSP + d] = kvb[((ktok0 + n) * NH_ + h) * (NOPE_ + VD_) + NOPE_ + d];
        }
        __syncthreads();

        // ---- scores: sc[4][4] = Q(rows ty*4..) . K(cols tx*4..) ----
        float sc[4][4];
#pragma unroll
        for (int i = 0; i < 4; i++)
#pragma unroll
            for (int j = 0; j < 4; j++) sc[i][j] = 0.f;

#pragma unroll 8
        for (int k = 0; k < QKD_; k++) {
            float a[4];
#pragma unroll
            for (int i = 0; i < 4; i++) a[i] = Qs[(ty * 4 + i) * QKD_ + k];
            const float4 b4 = *(const float4*)&Ks[k * KSP + tx * 4];
            const float bb[4] = {b4.x, b4.y, b4.z, b4.w};
#pragma unroll
            for (int i = 0; i < 4; i++)
#pragma unroll
                for (int j = 0; j < 4; j++) sc[i][j] = fmaf(a[i], bb[j], sc[i][j]);
        }

        // scale + causal mask (only diagonal block needs masking)
        if (kb == qb) {
#pragma unroll
            for (int i = 0; i < 4; i++) {
                const int qrow = ty * 4 + i;
#pragma unroll
                for (int j = 0; j < 4; j++) {
                    const int kcol = tx * 4 + j;
                    sc[i][j] = (kcol > qrow) ? -1e30f : sc[i][j] * scale;
                }
            }
        } else {
#pragma unroll
            for (int i = 0; i < 4; i++)
#pragma unroll
                for (int j = 0; j < 4; j++) sc[i][j] *= scale;
        }

        // ---- online softmax (row groups of 16 lanes: same ty, tx=0..15) ----
#pragma unroll
        for (int i = 0; i < 4; i++) {
            float mx = fmaxf(fmaxf(sc[i][0], sc[i][1]), fmaxf(sc[i][2], sc[i][3]));
#pragma unroll
            for (int off = 8; off >= 1; off >>= 1)
                mx = fmaxf(mx, __shfl_xor_sync(0xffffffffu, mx, off, 16));
            const float mnew  = fmaxf(m_i[i], mx);
            const float alpha = __expf(m_i[i] - mnew);
            m_i[i] = mnew;
            float rs = 0.f;
#pragma unroll
            for (int j = 0; j < 4; j++) {
                const float p = __expf(sc[i][j] - mnew);
                sc[i][j] = p;
                rs += p;
            }
#pragma unroll
            for (int off = 8; off >= 1; off >>= 1)
                rs += __shfl_xor_sync(0xffffffffu, rs, off, 16);
            l_i[i] = l_i[i] * alpha + rs;
#pragma unroll
            for (int j = 0; j < 8; j++) oacc[i][j] *= alpha;
        }

        // ---- stage P, then PV ----
#pragma unroll
        for (int i = 0; i < 4; i++)
#pragma unroll
            for (int j = 0; j < 4; j++)
                Ps[(ty * 4 + i) * KSP + tx * 4 + j] = sc[i][j];
        __syncthreads();

#pragma unroll 4
        for (int kk = 0; kk < BN_; kk++) {
            float p[4];
#pragma unroll
            for (int i = 0; i < 4; i++) p[i] = Ps[(ty * 4 + i) * KSP + kk];
            const float4 v0 = *(const float4*)&Vs[kk * VSP + tx * 8];
            const float4 v1 = *(const float4*)&Vs[kk * VSP + tx * 8 + 4];
            const float vv[8] = {v0.x, v0.y, v0.z, v0.w, v1.x, v1.y, v1.z, v1.w};
#pragma unroll
            for (int i = 0; i < 4; i++)
#pragma unroll
                for (int j = 0; j < 8; j++) oacc[i][j] = fmaf(p[i], vv[j], oacc[i][j]);
        }
        __syncthreads();
    }

    // write output: o[tok][h][128]
#pragma unroll
    for (int i = 0; i < 4; i++) {
        const float inv = 1.f / l_i[i];
        const size_t base = ((tok0 + ty * 4 + i) * NH_ + h) * VD_ + tx * 8;
#pragma unroll
        for (int j = 0; j < 8; j++) o[base + j] = oacc[i][j] * inv;
    }
}

// ============================================================================
// launch
// ============================================================================
extern "C" void kernel_launch(void* const* d_in, const int* in_sizes, int n_in,
                              void* d_out, int out_size)
{
    const float* x     = (const float*)d_in[0];
    const float* wq    = (const float*)d_in[1];
    const float* wkv_a = (const float*)d_in[2];
    const float* kvnw  = (const float*)d_in[3];
    const float* wkv_b = (const float*)d_in[4];
    const float* wo    = (const float*)d_in[5];
    const float* fc    = (const float*)d_in[6];
    const float* fs    = (const float*)d_in[7];
    float* out = (float*)d_out;

    float *q_p, *kv_p, *kvc_p, *kpe_p, *kvb_p, *attn_p;
    cudaGetSymbolAddress((void**)&q_p,    g_q);
    cudaGetSymbolAddress((void**)&kv_p,   g_kv);
    cudaGetSymbolAddress((void**)&kvc_p,  g_kvc);
    cudaGetSymbolAddress((void**)&kpe_p,  g_kpe);
    cudaGetSymbolAddress((void**)&kvb_p,  g_kvb);
    cudaGetSymbolAddress((void**)&attn_p, g_attn);

    // softmax scale with yarn mscale (MAX_LEN > ORIG_LEN)
    const double ms    = 0.1 * 1.0 * log(40.0) + 1.0;
    const float  scale = (float)(pow((double)QKD_, -0.5) * ms * ms);

    // 1. q = x @ wq^T : (4096,3072)   (used UN-rotated in attention, per reference)
    sgemm_nt<<<dim3((NH_ * QKD_ + 127) / 128, NTOK_ / 128), 256>>>(
        x, wq, q_p, NTOK_, NH_ * QKD_, DIM_);

    // 2. kv = x @ wkv_a^T : (4096,576)
    sgemm_nt<<<dim3((KVLORA_ + ROPE_ + 127) / 128, NTOK_ / 128), 256>>>(
        x, wkv_a, kv_p, NTOK_, KVLORA_ + ROPE_, DIM_);

    // 3. RMSNorm kv_c + RoPE k_pe
    kv_post_kernel<<<NTOK_, 128>>>(kv_p, kvnw, fc, fs, kvc_p, kpe_p);

    // 4. kvb = kv_c_norm @ wkv_b^T : (4096,4096)
    sgemm_nt<<<dim3((NH_ * (NOPE_ + VD_) + 127) / 128, NTOK_ / 128), 256>>>(
        kvc_p, wkv_b, kvb_p, NTOK_, NH_ * (NOPE_ + VD_), KVLORA_);

    // 5. causal attention
    cudaFuncSetAttribute(flash_attn_kernel,
                         cudaFuncAttributeMaxDynamicSharedMemorySize, FA_SMEM_BYTES);
    flash_attn_kernel<<<dim3(S_ / BM_, NH_, B_), 256, FA_SMEM_BYTES>>>(
        q_p, kvb_p, kpe_p, attn_p, scale);

    // 6. out = attn @ wo^T : (4096,2048)
    sgemm_nt<<<dim3((DIM_ + 127) / 128, NTOK_ / 128), 256>>>(
        attn_p, wo, out, NTOK_, DIM_, NH_ * VD_);
}

// round 13
// speedup vs baseline: 1.3085x; 1.3085x over previous
#include <cuda_runtime.h>
#include <cuda_bf16.h>
#include <math.h>
#include <cstdint>

// ---------------- problem constants ----------------
#define B_       2
#define S_       2048
#define DIM_     2048
#define NH_      16
#define QKD_     192     // NOPE(128) + ROPE(64)
#define NOPE_    128
#define ROPE_    64
#define VD_      128
#define KVLORA_  512
#define NTOK_    (B_ * S_)   // 4096

// ---------------- scratch (static device globals; no allocation) ----------------
__device__ float g_q   [NTOK_ * (NH_ * QKD_)];          // fp32, attention input
__device__ float g_kv  [NTOK_ * (KVLORA_ + ROPE_)];
__device__ float g_kpe [NTOK_ * ROPE_];
__device__ float g_kvb [NTOK_ * (NH_ * (NOPE_ + VD_))]; // fp32, attention input

// hi/lo bf16 decompositions (3xBF16 GEMM operands)
__device__ __nv_bfloat16 g_xh   [NTOK_ * DIM_];
__device__ __nv_bfloat16 g_xl   [NTOK_ * DIM_];
__device__ __nv_bfloat16 g_wqh  [(NH_ * QKD_) * DIM_];
__device__ __nv_bfloat16 g_wql  [(NH_ * QKD_) * DIM_];
__device__ __nv_bfloat16 g_wkvah[(KVLORA_ + ROPE_) * DIM_];
__device__ __nv_bfloat16 g_wkval[(KVLORA_ + ROPE_) * DIM_];
__device__ __nv_bfloat16 g_kvch [NTOK_ * KVLORA_];
__device__ __nv_bfloat16 g_kvcl [NTOK_ * KVLORA_];
__device__ __nv_bfloat16 g_wkvbh[(NH_ * (NOPE_ + VD_)) * KVLORA_];
__device__ __nv_bfloat16 g_wkvbl[(NH_ * (NOPE_ + VD_)) * KVLORA_];
__device__ __nv_bfloat16 g_atth [NTOK_ * (NH_ * VD_)];
__device__ __nv_bfloat16 g_attl [NTOK_ * (NH_ * VD_)];
__device__ __nv_bfloat16 g_woh  [DIM_ * (NH_ * VD_)];
__device__ __nv_bfloat16 g_wol  [DIM_ * (NH_ * VD_)];

// ============================================================================
// Warp-MMA helpers (portable PTX: works on compute_103 generic target)
// ============================================================================
__device__ __forceinline__ uint32_t smem_u32(const void* p) {
    uint32_t a;
    asm("{ .reg .u64 t; cvta.to.shared.u64 t, %1; cvt.u32.u64 %0, t; }"
        : "=r"(a) : "l"(p));
    return a;
}

__device__ __forceinline__ void ldsm_x4(uint32_t& r0, uint32_t& r1,
                                        uint32_t& r2, uint32_t& r3, uint32_t addr) {
    asm volatile("ldmatrix.sync.aligned.m8n8.x4.shared.b16 {%0,%1,%2,%3}, [%4];"
                 : "=r"(r0), "=r"(r1), "=r"(r2), "=r"(r3) : "r"(addr));
}

__device__ __forceinline__ void mma_16816(float* d, const uint32_t* a,
                                          uint32_t b0, uint32_t b1) {
    asm volatile(
        "mma.sync.aligned.m16n8k16.row.col.f32.bf16.bf16.f32 "
        "{%0,%1,%2,%3}, {%4,%5,%6,%7}, {%8,%9}, {%0,%1,%2,%3};"
        : "+f"(d[0]), "+f"(d[1]), "+f"(d[2]), "+f"(d[3])
        : "r"(a[0]), "r"(a[1]), "r"(a[2]), "r"(a[3]), "r"(b0), "r"(b1));
}

// ============================================================================
// 3xBF16 tensor-core GEMM via mma.sync:
//   C[M,N] = (Ah+Al)[M,K] * (Bh+Bl)[N,K]^T   (fp32 accumulate)
// CTA tile 128x128, K chunk 32, 256 threads = 8 warps (2x4), warp tile 64x32.
// SMEM tiles: [128][40] bf16 (80B row stride -> conflict-free ldmatrix).
// ============================================================================
#define GST 40   // smem row stride in bf16 elements (80 bytes)

__device__ __forceinline__ void load_chunk(__nv_bfloat16* __restrict__ dst,
                                           const __nv_bfloat16* __restrict__ src,
                                           int row0, int nrows, int K, int k0, int tid)
{
#pragma unroll
    for (int i = 0; i < 2; i++) {
        const int u = tid + i * 256;     // 0..511
        const int r = u >> 2;            // row 0..127
        const int s = u & 3;             // 16B segment 0..3
        uint4 v = make_uint4(0u, 0u, 0u, 0u);
        if (row0 + r < nrows)
            v = *(const uint4*)(src + (size_t)(row0 + r) * K + k0 + s * 8);
        *(uint4*)((char*)dst + r * (GST * 2) + s * 16) = v;
    }
}

__global__ __launch_bounds__(256, 2)
void bf3_gemm_mma(const __nv_bfloat16* __restrict__ Ah, const __nv_bfloat16* __restrict__ Al,
                  const __nv_bfloat16* __restrict__ Bh, const __nv_bfloat16* __restrict__ Bl,
                  float* __restrict__ C, int M, int N, int K)
{
    __shared__ __nv_bfloat16 smt[4][128][GST];   // Ah, Al, Bh, Bl chunks

    const int tid   = threadIdx.x;
    const int wid   = tid >> 5;
    const int lane  = tid & 31;
    const int wm    = wid & 1;          // warp row (2)
    const int wn    = wid >> 1;         // warp col (4)
    const int bm    = blockIdx.y * 128;
    const int bn    = blockIdx.x * 128;

    const uint32_t sb  = smem_u32(&smt[0][0][0]);
    const uint32_t tAh = sb;
    const uint32_t tAl = sb + 1 * 128 * GST * 2;
    const uint32_t tBh = sb + 2 * 128 * GST * 2;
    const uint32_t tBl = sb + 3 * 128 * GST * 2;

    // per-lane ldmatrix address bases (col part added per k-step)
    const int mat = lane >> 3, rr = lane & 7;
    // A x4 tile (16x16) at (row0, c0): mats (r,c): (0,0),(8,0),(0,8),(8,8)
    uint32_t aoff[4];
#pragma unroll
    for (int mt = 0; mt < 4; mt++) {
        const int row = wm * 64 + mt * 16 + rr + (mat & 1) * 8;
        aoff[mt] = row * (GST * 2) + (mat >> 1) * 16;
    }
    // B x4 covers two n-tiles (n0..n0+15): mats: (n0+rr,c0),(n0+rr,c0+8),(n0+8+rr,c0),(n0+8+rr,c0+8)
    uint32_t boff[2];
#pragma unroll
    for (int v = 0; v < 2; v++) {
        const int row = wn * 32 + v * 16 + rr + (mat >> 1) * 8;
        boff[v] = row * (GST * 2) + (mat & 1) * 16;
    }

    float acc[4][4][4];
#pragma unroll
    for (int i = 0; i < 4; i++)
#pragma unroll
        for (int j = 0; j < 4; j++)
#pragma unroll
            for (int r = 0; r < 4; r++) acc[i][j][r] = 0.f;

    for (int k0 = 0; k0 < K; k0 += 32) {
        load_chunk(&smt[0][0][0], Ah, bm, M, K, k0, tid);
        load_chunk(&smt[1][0][0], Al, bm, M, K, k0, tid);
        load_chunk(&smt[2][0][0], Bh, bn, N, K, k0, tid);
        load_chunk(&smt[3][0][0], Bl, bn, N, K, k0, tid);
        __syncthreads();

#pragma unroll
        for (int ks = 0; ks < 2; ks++) {
            const uint32_t kc = ks * 32;   // 16 bf16 = 32 bytes

            uint32_t af[4][4], bh[4][2], bl[4][2];
#pragma unroll
            for (int mt = 0; mt < 4; mt++)
                ldsm_x4(af[mt][0], af[mt][1], af[mt][2], af[mt][3],
                        tAh + aoff[mt] + kc);
#pragma unroll
            for (int v = 0; v < 2; v++) {
                ldsm_x4(bh[v*2][0], bh[v*2][1], bh[v*2+1][0], bh[v*2+1][1],
                        tBh + boff[v] + kc);
                ldsm_x4(bl[v*2][0], bl[v*2][1], bl[v*2+1][0], bl[v*2+1][1],
                        tBl + boff[v] + kc);
            }

            // ah * bh
#pragma unroll
            for (int mt = 0; mt < 4; mt++)
#pragma unroll
                for (int nt = 0; nt < 4; nt++)
                    mma_16816(acc[mt][nt], af[mt], bh[nt][0], bh[nt][1]);
            // ah * bl
#pragma unroll
            for (int mt = 0; mt < 4; mt++)
#pragma unroll
                for (int nt = 0; nt < 4; nt++)
                    mma_16816(acc[mt][nt], af[mt], bl[nt][0], bl[nt][1]);
            // al * bh (reuse af registers)
#pragma unroll
            for (int mt = 0; mt < 4; mt++)
                ldsm_x4(af[mt][0], af[mt][1], af[mt][2], af[mt][3],
                        tAl + aoff[mt] + kc);
#pragma unroll
            for (int mt = 0; mt < 4; mt++)
#pragma unroll
                for (int nt = 0; nt < 4; nt++)
                    mma_16816(acc[mt][nt], af[mt], bh[nt][0], bh[nt][1]);
        }
        __syncthreads();
    }

    // epilogue: d0,d1 -> (row, col..col+1); d2,d3 -> (row+8, col..col+1)
    const int g = lane >> 2, t = lane & 3;
#pragma unroll
    for (int mt = 0; mt < 4; mt++) {
        const int gm = bm + wm * 64 + mt * 16 + g;
#pragma unroll
        for (int nt = 0; nt < 4; nt++) {
            const int gc = bn + wn * 32 + nt * 8 + 2 * t;
            if (gc < N) {
                *(float2*)(C + (size_t)gm * N + gc) =
                    make_float2(acc[mt][nt][0], acc[mt][nt][1]);
                *(float2*)(C + (size_t)(gm + 8) * N + gc) =
                    make_float2(acc[mt][nt][2], acc[mt][nt][3]);
            }
        }
    }
}

// ============================================================================
// fp32 -> (hi, lo) bf16 decomposition
// ============================================================================
__global__ void cvt_hilo(const float* __restrict__ x,
                         __nv_bfloat16* __restrict__ h,
                         __nv_bfloat16* __restrict__ l, int n)
{
    const int i = blockIdx.x * 256 + threadIdx.x;
    if (i < n) {
        const float v = x[i];
        const __nv_bfloat16 hv = __float2bfloat16(v);
        h[i] = hv;
        l[i] = __float2bfloat16(v - __bfloat162float(hv));
    }
}

// ============================================================================
// Per-token: RMSNorm(kv_c) -> hi/lo bf16 ; RoPE(k_pe) -> g_kpe.
// (reference applies RoPE only to k_pe; q stays un-rotated)
// ============================================================================
__global__ __launch_bounds__(128) void kv_post_kernel(
    const float* __restrict__ kv, const float* __restrict__ kvnw,
    const float* __restrict__ fc, const float* __restrict__ fs,
    __nv_bfloat16* __restrict__ kvch, __nv_bfloat16* __restrict__ kvcl,
    float* __restrict__ kpe)
{
    const int tok = blockIdx.x;
    const int s   = tok & (S_ - 1);
    const float* row = kv + (size_t)tok * (KVLORA_ + ROPE_);

    __shared__ float red[4];
    float ss = 0.f;
    for (int d = threadIdx.x; d < KVLORA_; d += 128) {
        const float v = row[d];
        ss += v * v;
    }
#pragma unroll
    for (int off = 16; off; off >>= 1) ss += __shfl_xor_sync(0xffffffffu, ss, off);
    if ((threadIdx.x & 31) == 0) red[threadIdx.x >> 5] = ss;
    __syncthreads();
    const float tot = red[0] + red[1] + red[2] + red[3];
    const float rn  = rsqrtf(tot / (float)KVLORA_ + 1e-6f);

    for (int d = threadIdx.x; d < KVLORA_; d += 128) {
        const float y = row[d] * rn * kvnw[d];
        const __nv_bfloat16 hv = __float2bfloat16(y);
        kvch[(size_t)tok * KVLORA_ + d] = hv;
        kvcl[(size_t)tok * KVLORA_ + d] = __float2bfloat16(y - __bfloat162float(hv));
    }

    if (threadIdx.x < 32) {
        const int p  = threadIdx.x;
        const float xr = row[KVLORA_ + 2 * p];
        const float xi = row[KVLORA_ + 2 * p + 1];
        const float c  = fc[s * 32 + p];
        const float sn = fs[s * 32 + p];
        kpe[(size_t)tok * ROPE_ + 2 * p]     = xr * c - xi * sn;
        kpe[(size_t)tok * ROPE_ + 2 * p + 1] = xr * sn + xi * c;
    }
}

// ============================================================================
// Causal flash attention (fp32 SIMT), transposed Qs/Ps for float4 inner loops.
// grid = (S/64, NH, B), 256 threads (16x16). Emits hi/lo bf16 output.
// ============================================================================
#define BM_ 64
#define BN_ 64
#define QSP 68   // Qs [192][68]  ([d][m])
#define KSP 68   // Ks [192][68]  ([d][n])
#define VSP 132  // Vs [64][132]  ([n][d])
#define PSP 68   // Ps [64][68]   ([kk][m])

#define FA_SMEM_FLOATS (QKD_*QSP + QKD_*KSP + BN_*VSP + BM_*PSP)
#define FA_SMEM_BYTES  (FA_SMEM_FLOATS * 4)

__global__ __launch_bounds__(256) void flash_attn_kernel(
    const float* __restrict__ q,    // (tok, head, 192) -- UN-rotated, per reference
    const float* __restrict__ kvb,  // (tok, head, 256)  [k_nope | v]
    const float* __restrict__ kpe,  // (tok, 64)         -- rotated
    __nv_bfloat16* __restrict__ oh,
    __nv_bfloat16* __restrict__ ol,
    float scale)
{
    extern __shared__ float sm[];
    float* Qs = sm;
    float* Ks = Qs + QKD_ * QSP;
    float* Vs = Ks + QKD_ * KSP;
    float* Ps = Vs + BN_ * VSP;

    const int qb  = blockIdx.x;
    const int h   = blockIdx.y;
    const int b   = blockIdx.z;
    const int tid = threadIdx.x;
    const int tx  = tid & 15;
    const int ty  = tid >> 4;

    const size_t tok0 = (size_t)b * S_ + (size_t)qb * BM_;

    for (int idx = tid; idx < BM_ * QKD_; idx += 256) {
        const int m = idx / QKD_, d = idx - m * QKD_;
        Qs[d * QSP + m] = q[((tok0 + m) * NH_ + h) * QKD_ + d];
    }

    float m_i[4], l_i[4], oacc[4][8];
#pragma unroll
    for (int i = 0; i < 4; i++) {
        m_i[i] = -1e30f; l_i[i] = 0.f;
#pragma unroll
        for (int j = 0; j < 8; j++) oacc[i][j] = 0.f;
    }
    __syncthreads();

    for (int kb = 0; kb <= qb; kb++) {
        const size_t ktok0 = (size_t)b * S_ + (size_t)kb * BN_;

        for (int idx = tid; idx < BN_ * QKD_; idx += 256) {
            const int n = idx / QKD_, d = idx - n * QKD_;
            float v;
            if (d < NOPE_) v = kvb[((ktok0 + n) * NH_ + h) * (NOPE_ + VD_) + d];
            else           v = kpe[(ktok0 + n) * ROPE_ + (d - NOPE_)];
            Ks[d * KSP + n] = v;
        }
        for (int idx = tid; idx < BN_ * VD_; idx += 256) {
            const int n = idx >> 7, d = idx & 127;
            Vs[n * VSP + d] = kvb[((ktok0 + n) * NH_ + h) * (NOPE_ + VD_) + NOPE_ + d];
        }
        __syncthreads();

        float sc[4][4];
#pragma unroll
        for (int i = 0; i < 4; i++)
#pragma unroll
            for (int j = 0; j < 4; j++) sc[i][j] = 0.f;

#pragma unroll 8
        for (int k = 0; k < QKD_; k++) {
            const float4 a4 = *(const float4*)&Qs[k * QSP + ty * 4];
            const float4 b4 = *(const float4*)&Ks[k * KSP + tx * 4];
            const float aa[4] = {a4.x, a4.y, a4.z, a4.w};
            const float bb[4] = {b4.x, b4.y, b4.z, b4.w};
#pragma unroll
            for (int i = 0; i < 4; i++)
#pragma unroll
                for (int j = 0; j < 4; j++) sc[i][j] = fmaf(aa[i], bb[j], sc[i][j]);
        }

        if (kb == qb) {
#pragma unroll
            for (int i = 0; i < 4; i++) {
                const int qrow = ty * 4 + i;
#pragma unroll
                for (int j = 0; j < 4; j++) {
                    const int kcol = tx * 4 + j;
                    sc[i][j] = (kcol > qrow) ? -1e30f : sc[i][j] * scale;
                }
            }
        } else {
#pragma unroll
            for (int i = 0; i < 4; i++)
#pragma unroll
                for (int j = 0; j < 4; j++) sc[i][j] *= scale;
        }

#pragma unroll
        for (int i = 0; i < 4; i++) {
            float mx = fmaxf(fmaxf(sc[i][0], sc[i][1]), fmaxf(sc[i][2], sc[i][3]));
#pragma unroll
            for (int off = 8; off >= 1; off >>= 1)
                mx = fmaxf(mx, __shfl_xor_sync(0xffffffffu, mx, off, 16));
            const float mnew  = fmaxf(m_i[i], mx);
            const float alpha = __expf(m_i[i] - mnew);
            m_i[i] = mnew;
            float rs = 0.f;
#pragma unroll
            for (int j = 0; j < 4; j++) {
                const float p = __expf(sc[i][j] - mnew);
                sc[i][j] = p;
                rs += p;
            }
#pragma unroll
            for (int off = 8; off >= 1; off >>= 1)
                rs += __shfl_xor_sync(0xffffffffu, rs, off, 16);
            l_i[i] = l_i[i] * alpha + rs;
#pragma unroll
            for (int j = 0; j < 8; j++) oacc[i][j] *= alpha;
        }

#pragma unroll
        for (int i = 0; i < 4; i++)
#pragma unroll
            for (int j = 0; j < 4; j++)
                Ps[(tx * 4 + j) * PSP + ty * 4 + i] = sc[i][j];
        __syncthreads();

#pragma unroll 4
        for (int kk = 0; kk < BN_; kk++) {
            const float4 p4 = *(const float4*)&Ps[kk * PSP + ty * 4];
            const float pp[4] = {p4.x, p4.y, p4.z, p4.w};
            const float4 v0 = *(const float4*)&Vs[kk * VSP + tx * 8];
            const float4 v1 = *(const float4*)&Vs[kk * VSP + tx * 8 + 4];
            const float vv[8] = {v0.x, v0.y, v0.z, v0.w, v1.x, v1.y, v1.z, v1.w};
#pragma unroll
            for (int i = 0; i < 4; i++)
#pragma unroll
                for (int j = 0; j < 8; j++) oacc[i][j] = fmaf(pp[i], vv[j], oacc[i][j]);
        }
        __syncthreads();
    }

#pragma unroll
    for (int i = 0; i < 4; i++) {
        const float inv = 1.f / l_i[i];
        const size_t base = ((tok0 + ty * 4 + i) * NH_ + h) * VD_ + tx * 8;
#pragma unroll
        for (int j = 0; j < 8; j++) {
            const float v = oacc[i][j] * inv;
            const __nv_bfloat16 hv = __float2bfloat16(v);
            oh[base + j] = hv;
            ol[base + j] = __float2bfloat16(v - __bfloat162float(hv));
        }
    }
}

// ============================================================================
// launch
// ============================================================================
extern "C" void kernel_launch(void* const* d_in, const int* in_sizes, int n_in,
                              void* d_out, int out_size)
{
    const float* x     = (const float*)d_in[0];
    const float* wq    = (const float*)d_in[1];
    const float* wkv_a = (const float*)d_in[2];
    const float* kvnw  = (const float*)d_in[3];
    const float* wkv_b = (const float*)d_in[4];
    const float* wo    = (const float*)d_in[5];
    const float* fc    = (const float*)d_in[6];
    const float* fs    = (const float*)d_in[7];
    float* out = (float*)d_out;

    float *q_p, *kv_p, *kpe_p, *kvb_p;
    __nv_bfloat16 *xh, *xl, *wqh, *wql, *wkvah, *wkval, *kvch, *kvcl;
    __nv_bfloat16 *wkvbh, *wkvbl, *atth, *attl, *woh, *wol;
    cudaGetSymbolAddress((void**)&q_p,   g_q);
    cudaGetSymbolAddress((void**)&kv_p,  g_kv);
    cudaGetSymbolAddress((void**)&kpe_p, g_kpe);
    cudaGetSymbolAddress((void**)&kvb_p, g_kvb);
    cudaGetSymbolAddress((void**)&xh,    g_xh);
    cudaGetSymbolAddress((void**)&xl,    g_xl);
    cudaGetSymbolAddress((void**)&wqh,   g_wqh);
    cudaGetSymbolAddress((void**)&wql,   g_wql);
    cudaGetSymbolAddress((void**)&wkvah, g_wkvah);
    cudaGetSymbolAddress((void**)&wkval, g_wkval);
    cudaGetSymbolAddress((void**)&kvch,  g_kvch);
    cudaGetSymbolAddress((void**)&kvcl,  g_kvcl);
    cudaGetSymbolAddress((void**)&wkvbh, g_wkvbh);
    cudaGetSymbolAddress((void**)&wkvbl, g_wkvbl);
    cudaGetSymbolAddress((void**)&atth,  g_atth);
    cudaGetSymbolAddress((void**)&attl,  g_attl);
    cudaGetSymbolAddress((void**)&woh,   g_woh);
    cudaGetSymbolAddress((void**)&wol,   g_wol);

    // softmax scale with yarn mscale (MAX_LEN > ORIG_LEN)
    const double ms    = 0.1 * 1.0 * log(40.0) + 1.0;
    const float  scale = (float)(pow((double)QKD_, -0.5) * ms * ms);

    cudaFuncSetAttribute(flash_attn_kernel,
                         cudaFuncAttributeMaxDynamicSharedMemorySize, FA_SMEM_BYTES);

    // 0. hi/lo decompositions of x and all weights
    {
        int n;
        n = NTOK_ * DIM_;                    cvt_hilo<<<(n + 255) / 256, 256>>>(x,     xh,    xl,    n);
        n = (NH_ * QKD_) * DIM_;             cvt_hilo<<<(n + 255) / 256, 256>>>(wq,    wqh,   wql,   n);
        n = (KVLORA_ + ROPE_) * DIM_;        cvt_hilo<<<(n + 255) / 256, 256>>>(wkv_a, wkvah, wkval, n);
        n = (NH_ * (NOPE_ + VD_)) * KVLORA_; cvt_hilo<<<(n + 255) / 256, 256>>>(wkv_b, wkvbh, wkvbl, n);
        n = DIM_ * (NH_ * VD_);              cvt_hilo<<<(n + 255) / 256, 256>>>(wo,    woh,   wol,   n);
    }

    // 1. q = x @ wq^T : (4096, 3072), K=2048
    bf3_gemm_mma<<<dim3((NH_ * QKD_ + 127) / 128, NTOK_ / 128), 256>>>(
        xh, xl, wqh, wql, q_p, NTOK_, NH_ * QKD_, DIM_);

    // 2. kv = x @ wkv_a^T : (4096, 576), K=2048
    bf3_gemm_mma<<<dim3((KVLORA_ + ROPE_ + 127) / 128, NTOK_ / 128), 256>>>(
        xh, xl, wkvah, wkval, kv_p, NTOK_, KVLORA_ + ROPE_, DIM_);

    // 3. RMSNorm kv_c (-> hi/lo) + RoPE k_pe
    kv_post_kernel<<<NTOK_, 128>>>(kv_p, kvnw, fc, fs, kvch, kvcl, kpe_p);

    // 4. kvb = kv_c_norm @ wkv_b^T : (4096, 4096), K=512
    bf3_gemm_mma<<<dim3((NH_ * (NOPE_ + VD_) + 127) / 128, NTOK_ / 128), 256>>>(
        kvch, kvcl, wkvbh, wkvbl, kvb_p, NTOK_, NH_ * (NOPE_ + VD_), KVLORA_);

    // 5. causal attention (-> hi/lo)
    flash_attn_kernel<<<dim3(S_ / BM_, NH_, B_), 256, FA_SMEM_BYTES>>>(
        q_p, kvb_p, kpe_p, atth, attl, scale);

    // 6. out = attn @ wo^T : (4096, 2048), K=2048
    bf3_gemm_mma<<<dim3((DIM_ + 127) / 128, NTOK_ / 128), 256>>>(
        atth, attl, woh, wol, out, NTOK_, DIM_, NH_ * VD_);
}

// round 16
// speedup vs baseline: 3.1046x; 2.3726x over previous
#include <cuda_runtime.h>
#include <cuda_bf16.h>
#include <math.h>
#include <cstdint>

// ---------------- problem constants ----------------
#define B_       2
#define S_       2048
#define DIM_     2048
#define NH_      16
#define QKD_     192     // NOPE(128) + ROPE(64)
#define NOPE_    128
#define ROPE_    64
#define VD_      128
#define KVLORA_  512
#define NTOK_    (B_ * S_)   // 4096

// ---------------- scratch (static device globals; no allocation) ----------------
__device__ float g_q   [NTOK_ * (NH_ * QKD_)];          // fp32 q (tok, head, 192)
__device__ float g_kv  [NTOK_ * (KVLORA_ + ROPE_)];
__device__ float g_kpe [NTOK_ * ROPE_];
__device__ float g_kvb [NTOK_ * (NH_ * (NOPE_ + VD_))]; // fp32 (tok, head, 256)

// hi/lo bf16 decompositions (3xBF16 GEMM operands)
__device__ __nv_bfloat16 g_xh   [NTOK_ * DIM_];
__device__ __nv_bfloat16 g_xl   [NTOK_ * DIM_];
__device__ __nv_bfloat16 g_wqh  [(NH_ * QKD_) * DIM_];
__device__ __nv_bfloat16 g_wql  [(NH_ * QKD_) * DIM_];
__device__ __nv_bfloat16 g_wkvah[(KVLORA_ + ROPE_) * DIM_];
__device__ __nv_bfloat16 g_wkval[(KVLORA_ + ROPE_) * DIM_];
__device__ __nv_bfloat16 g_kvch [NTOK_ * KVLORA_];
__device__ __nv_bfloat16 g_kvcl [NTOK_ * KVLORA_];
__device__ __nv_bfloat16 g_wkvbh[(NH_ * (NOPE_ + VD_)) * KVLORA_];
__device__ __nv_bfloat16 g_wkvbl[(NH_ * (NOPE_ + VD_)) * KVLORA_];
__device__ __nv_bfloat16 g_atth [NTOK_ * (NH_ * VD_)];
__device__ __nv_bfloat16 g_attl [NTOK_ * (NH_ * VD_)];
__device__ __nv_bfloat16 g_woh  [DIM_ * (NH_ * VD_)];
__device__ __nv_bfloat16 g_wol  [DIM_ * (NH_ * VD_)];

// flash-attention bf16 operands: K (b,h,s,192) and V^T (b,h,d,s)
__device__ __nv_bfloat16 g_kh  [B_ * NH_ * S_ * QKD_];
__device__ __nv_bfloat16 g_kl  [B_ * NH_ * S_ * QKD_];
__device__ __nv_bfloat16 g_vth [B_ * NH_ * VD_ * S_];
__device__ __nv_bfloat16 g_vtl [B_ * NH_ * VD_ * S_];

// ============================================================================
// Warp-MMA helpers (portable PTX: works on compute_103 generic target)
// ============================================================================
__device__ __forceinline__ uint32_t smem_u32(const void* p) {
    uint32_t a;
    asm("{ .reg .u64 t; cvta.to.shared.u64 t, %1; cvt.u32.u64 %0, t; }"
        : "=r"(a) : "l"(p));
    return a;
}

__device__ __forceinline__ void ldsm_x4(uint32_t& r0, uint32_t& r1,
                                        uint32_t& r2, uint32_t& r3, uint32_t addr) {
    asm volatile("ldmatrix.sync.aligned.m8n8.x4.shared.b16 {%0,%1,%2,%3}, [%4];"
                 : "=r"(r0), "=r"(r1), "=r"(r2), "=r"(r3) : "r"(addr));
}

__device__ __forceinline__ void mma_16816(float* d, const uint32_t* a,
                                          uint32_t b0, uint32_t b1) {
    asm volatile(
        "mma.sync.aligned.m16n8k16.row.col.f32.bf16.bf16.f32 "
        "{%0,%1,%2,%3}, {%4,%5,%6,%7}, {%8,%9}, {%0,%1,%2,%3};"
        : "+f"(d[0]), "+f"(d[1]), "+f"(d[2]), "+f"(d[3])
        : "r"(a[0]), "r"(a[1]), "r"(a[2]), "r"(a[3]), "r"(b0), "r"(b1));
}

// pack two fp32 -> bf16x2 (lo in low half) ; rounding = RN (matches __float2bfloat16)
__device__ __forceinline__ uint32_t packbf(float lo, float hi) {
    uint32_t r;
    asm("cvt.rn.bf16x2.f32 %0, %1, %2;" : "=r"(r) : "f"(hi), "f"(lo));
    return r;
}

// ============================================================================
// 3xBF16 tensor-core GEMM via mma.sync (unchanged from passing round 13)
// ============================================================================
#define GST 40

__device__ __forceinline__ void load_chunk(__nv_bfloat16* __restrict__ dst,
                                           const __nv_bfloat16* __restrict__ src,
                                           int row0, int nrows, int K, int k0, int tid)
{
#pragma unroll
    for (int i = 0; i < 2; i++) {
        const int u = tid + i * 256;
        const int r = u >> 2;
        const int s = u & 3;
        uint4 v = make_uint4(0u, 0u, 0u, 0u);
        if (row0 + r < nrows)
            v = *(const uint4*)(src + (size_t)(row0 + r) * K + k0 + s * 8);
        *(uint4*)((char*)dst + r * (GST * 2) + s * 16) = v;
    }
}

__global__ __launch_bounds__(256, 2)
void bf3_gemm_mma(const __nv_bfloat16* __restrict__ Ah, const __nv_bfloat16* __restrict__ Al,
                  const __nv_bfloat16* __restrict__ Bh, const __nv_bfloat16* __restrict__ Bl,
                  float* __restrict__ C, int M, int N, int K)
{
    __shared__ __nv_bfloat16 smt[4][128][GST];

    const int tid   = threadIdx.x;
    const int wid   = tid >> 5;
    const int lane  = tid & 31;
    const int wm    = wid & 1;
    const int wn    = wid >> 1;
    const int bm    = blockIdx.y * 128;
    const int bn    = blockIdx.x * 128;

    const uint32_t sb  = smem_u32(&smt[0][0][0]);
    const uint32_t tAh = sb;
    const uint32_t tAl = sb + 1 * 128 * GST * 2;
    const uint32_t tBh = sb + 2 * 128 * GST * 2;
    const uint32_t tBl = sb + 3 * 128 * GST * 2;

    const int mat = lane >> 3, rr = lane & 7;
    uint32_t aoff[4];
#pragma unroll
    for (int mt = 0; mt < 4; mt++) {
        const int row = wm * 64 + mt * 16 + rr + (mat & 1) * 8;
        aoff[mt] = row * (GST * 2) + (mat >> 1) * 16;
    }
    uint32_t boff[2];
#pragma unroll
    for (int v = 0; v < 2; v++) {
        const int row = wn * 32 + v * 16 + rr + (mat >> 1) * 8;
        boff[v] = row * (GST * 2) + (mat & 1) * 16;
    }

    float acc[4][4][4];
#pragma unroll
    for (int i = 0; i < 4; i++)
#pragma unroll
        for (int j = 0; j < 4; j++)
#pragma unroll
            for (int r = 0; r < 4; r++) acc[i][j][r] = 0.f;

    for (int k0 = 0; k0 < K; k0 += 32) {
        load_chunk(&smt[0][0][0], Ah, bm, M, K, k0, tid);
        load_chunk(&smt[1][0][0], Al, bm, M, K, k0, tid);
        load_chunk(&smt[2][0][0], Bh, bn, N, K, k0, tid);
        load_chunk(&smt[3][0][0], Bl, bn, N, K, k0, tid);
        __syncthreads();

#pragma unroll
        for (int ks = 0; ks < 2; ks++) {
            const uint32_t kc = ks * 32;
            uint32_t af[4][4], bh[4][2], bl[4][2];
#pragma unroll
            for (int mt = 0; mt < 4; mt++)
                ldsm_x4(af[mt][0], af[mt][1], af[mt][2], af[mt][3], tAh + aoff[mt] + kc);
#pragma unroll
            for (int v = 0; v < 2; v++) {
                ldsm_x4(bh[v*2][0], bh[v*2][1], bh[v*2+1][0], bh[v*2+1][1], tBh + boff[v] + kc);
                ldsm_x4(bl[v*2][0], bl[v*2][1], bl[v*2+1][0], bl[v*2+1][1], tBl + boff[v] + kc);
            }
#pragma unroll
            for (int mt = 0; mt < 4; mt++)
#pragma unroll
                for (int nt = 0; nt < 4; nt++)
                    mma_16816(acc[mt][nt], af[mt], bh[nt][0], bh[nt][1]);
#pragma unroll
            for (int mt = 0; mt < 4; mt++)
#pragma unroll
                for (int nt = 0; nt < 4; nt++)
                    mma_16816(acc[mt][nt], af[mt], bl[nt][0], bl[nt][1]);
#pragma unroll
            for (int mt = 0; mt < 4; mt++)
                ldsm_x4(af[mt][0], af[mt][1], af[mt][2], af[mt][3], tAl + aoff[mt] + kc);
#pragma unroll
            for (int mt = 0; mt < 4; mt++)
#pragma unroll
                for (int nt = 0; nt < 4; nt++)
                    mma_16816(acc[mt][nt], af[mt], bh[nt][0], bh[nt][1]);
        }
        __syncthreads();
    }

    const int g = lane >> 2, t = lane & 3;
#pragma unroll
    for (int mt = 0; mt < 4; mt++) {
        const int gm = bm + wm * 64 + mt * 16 + g;
#pragma unroll
        for (int nt = 0; nt < 4; nt++) {
            const int gc = bn + wn * 32 + nt * 8 + 2 * t;
            if (gc < N) {
                *(float2*)(C + (size_t)gm * N + gc) =
                    make_float2(acc[mt][nt][0], acc[mt][nt][1]);
                *(float2*)(C + (size_t)(gm + 8) * N + gc) =
                    make_float2(acc[mt][nt][2], acc[mt][nt][3]);
            }
        }
    }
}

// ============================================================================
// fp32 -> (hi, lo) bf16 decomposition
// ============================================================================
__global__ void cvt_hilo(const float* __restrict__ x,
                         __nv_bfloat16* __restrict__ h,
                         __nv_bfloat16* __restrict__ l, int n)
{
    const int i = blockIdx.x * 256 + threadIdx.x;
    if (i < n) {
        const float v = x[i];
        const __nv_bfloat16 hv = __float2bfloat16(v);
        h[i] = hv;
        l[i] = __float2bfloat16(v - __bfloat162float(hv));
    }
}

// ============================================================================
// Per-token: RMSNorm(kv_c) -> hi/lo bf16 ; RoPE(k_pe) -> g_kpe.
// (reference applies RoPE only to k_pe; q stays un-rotated)
// ============================================================================
__global__ __launch_bounds__(128) void kv_post_kernel(
    const float* __restrict__ kv, const float* __restrict__ kvnw,
    const float* __restrict__ fc, const float* __restrict__ fs,
    __nv_bfloat16* __restrict__ kvch, __nv_bfloat16* __restrict__ kvcl,
    float* __restrict__ kpe)
{
    const int tok = blockIdx.x;
    const int s   = tok & (S_ - 1);
    const float* row = kv + (size_t)tok * (KVLORA_ + ROPE_);

    __shared__ float red[4];
    float ss = 0.f;
    for (int d = threadIdx.x; d < KVLORA_; d += 128) {
        const float v = row[d];
        ss += v * v;
    }
#pragma unroll
    for (int off = 16; off; off >>= 1) ss += __shfl_xor_sync(0xffffffffu, ss, off);
    if ((threadIdx.x & 31) == 0) red[threadIdx.x >> 5] = ss;
    __syncthreads();
    const float tot = red[0] + red[1] + red[2] + red[3];
    const float rn  = rsqrtf(tot / (float)KVLORA_ + 1e-6f);

    for (int d = threadIdx.x; d < KVLORA_; d += 128) {
        const float y = row[d] * rn * kvnw[d];
        const __nv_bfloat16 hv = __float2bfloat16(y);
        kvch[(size_t)tok * KVLORA_ + d] = hv;
        kvcl[(size_t)tok * KVLORA_ + d] = __float2bfloat16(y - __bfloat162float(hv));
    }

    if (threadIdx.x < 32) {
        const int p  = threadIdx.x;
        const float xr = row[KVLORA_ + 2 * p];
        const float xi = row[KVLORA_ + 2 * p + 1];
        const float c  = fc[s * 32 + p];
        const float sn = fs[s * 32 + p];
        kpe[(size_t)tok * ROPE_ + 2 * p]     = xr * c - xi * sn;
        kpe[(size_t)tok * ROPE_ + 2 * p + 1] = xr * sn + xi * c;
    }
}

// ============================================================================
// prep_k: build K = [k_nope | k_pe] hi/lo bf16, layout (b, h, s, 192)
// ============================================================================
__global__ void prep_k(const float* __restrict__ kvb, const float* __restrict__ kpe,
                       __nv_bfloat16* __restrict__ kh, __nv_bfloat16* __restrict__ kl)
{
    const int i = blockIdx.x * 256 + threadIdx.x;
    const int total = B_ * NH_ * S_ * QKD_;
    if (i >= total) return;
    const int d  = i % QKD_;
    const int sr = i / QKD_;
    const int s  = sr & (S_ - 1);
    const int bh = sr >> 11;
    const int b  = bh >> 4, h = bh & 15;
    const int tok = b * S_ + s;
    float v;
    if (d < NOPE_) v = kvb[((size_t)tok * NH_ + h) * (NOPE_ + VD_) + d];
    else           v = kpe[(size_t)tok * ROPE_ + d - NOPE_];
    const __nv_bfloat16 hv = __float2bfloat16(v);
    kh[i] = hv;
    kl[i] = __float2bfloat16(v - __bfloat162float(hv));
}

// ============================================================================
// prep_vt: V^T hi/lo bf16, layout (b, h, d, s). Tile transpose via smem.
// grid = (S/64, VD/64, B*NH), 256 threads.
// ============================================================================
__global__ __launch_bounds__(256) void prep_vt(const float* __restrict__ kvb,
                                               __nv_bfloat16* __restrict__ vth,
                                               __nv_bfloat16* __restrict__ vtl)
{
    __shared__ float tile[64][65];
    const int st = blockIdx.x, dt = blockIdx.y, bh = blockIdx.z;
    const int b = bh >> 4, h = bh & 15;
    const int tid = threadIdx.x;

#pragma unroll
    for (int k = 0; k < 16; k++) {
        const int idx = tid + k * 256;
        const int i = idx >> 6, j = idx & 63;
        const int tok = b * S_ + st * 64 + i;
        tile[i][j] = kvb[((size_t)tok * NH_ + h) * (NOPE_ + VD_) + NOPE_ + dt * 64 + j];
    }
    __syncthreads();
#pragma unroll
    for (int k = 0; k < 16; k++) {
        const int idx = tid + k * 256;
        const int j = idx >> 6, i = idx & 63;
        const float v = tile[i][j];
        const __nv_bfloat16 hv = __float2bfloat16(v);
        const size_t o = ((size_t)bh * VD_ + dt * 64 + j) * S_ + st * 64 + i;
        vth[o] = hv;
        vtl[o] = __float2bfloat16(v - __bfloat162float(hv));
    }
}

// ============================================================================
// Tensor-core causal flash attention (3xBF16 QK and PV, fp32 softmax).
// grid = (S/64, NH, B), 128 threads = 4 warps, warp owns 16 query rows.
// SMEM: Q hi/lo [64][200], K hi/lo [64][200], V^T hi/lo [128][72] bf16.
// ============================================================================
#define QS 200
#define VS 72
#define FA2_SMEM ((4 * 64 * QS + 2 * 128 * VS) * 2)

__global__ __launch_bounds__(128) void flash_mma(
    const float* __restrict__ q,
    const __nv_bfloat16* __restrict__ kh_g, const __nv_bfloat16* __restrict__ kl_g,
    const __nv_bfloat16* __restrict__ vth_g, const __nv_bfloat16* __restrict__ vtl_g,
    __nv_bfloat16* __restrict__ oh, __nv_bfloat16* __restrict__ ol,
    float scale)
{
    extern __shared__ __nv_bfloat16 sbm[];
    __nv_bfloat16* Qh = sbm;
    __nv_bfloat16* Ql = sbm + 64 * QS;
    __nv_bfloat16* Kh = sbm + 2 * 64 * QS;
    __nv_bfloat16* Kl = sbm + 3 * 64 * QS;
    __nv_bfloat16* Vh = sbm + 4 * 64 * QS;
    __nv_bfloat16* Vl = sbm + 4 * 64 * QS + 128 * VS;

    const int qb = blockIdx.x, h = blockIdx.y, b = blockIdx.z;
    const int tid = threadIdx.x, wid = tid >> 5, lane = tid & 31;
    const int g = lane >> 2, t4 = lane & 3;
    const int mat = lane >> 3, rr = lane & 7;
    const int m0 = wid * 16;
    const size_t tok0 = (size_t)b * S_ + (size_t)qb * 64;
    const size_t bh   = (size_t)b * NH_ + h;

    const uint32_t uQh = smem_u32(Qh), uQl = smem_u32(Ql);
    const uint32_t uKh = smem_u32(Kh), uKl = smem_u32(Kl);
    const uint32_t uVh = smem_u32(Vh), uVl = smem_u32(Vl);

    // ldmatrix lane-address components (identical recipe to the passing GEMM)
    const uint32_t qbase = (uint32_t)((m0 + rr + (mat & 1) * 8) * (QS * 2) + (mat >> 1) * 16);
    const uint32_t krow  = (uint32_t)((rr + (mat >> 1) * 8) * (QS * 2) + (mat & 1) * 16);
    const uint32_t vrow  = (uint32_t)((rr + (mat >> 1) * 8) * (VS * 2) + (mat & 1) * 16);

    // ---- stage Q (fp32 -> hi/lo bf16), once ----
    for (int idx = tid; idx < 64 * 48; idx += 128) {
        const int m = idx / 48, seg = idx - m * 48;
        const float4 v = *(const float4*)(q + ((tok0 + m) * NH_ + h) * QKD_ + seg * 4);
        const uint32_t h01 = packbf(v.x, v.y);
        const uint32_t h23 = packbf(v.z, v.w);
        const float r0 = v.x - __bfloat162float(__float2bfloat16(v.x));
        const float r1 = v.y - __bfloat162float(__float2bfloat16(v.y));
        const float r2 = v.z - __bfloat162float(__float2bfloat16(v.z));
        const float r3 = v.w - __bfloat162float(__float2bfloat16(v.w));
        *(uint32_t*)&Qh[m * QS + seg * 4]     = h01;
        *(uint32_t*)&Qh[m * QS + seg * 4 + 2] = h23;
        *(uint32_t*)&Ql[m * QS + seg * 4]     = packbf(r0, r1);
        *(uint32_t*)&Ql[m * QS + seg * 4 + 2] = packbf(r2, r3);
    }

    float m_i[2] = {-1e30f, -1e30f}, l_i[2] = {0.f, 0.f};
    float oacc[16][4];
#pragma unroll
    for (int i = 0; i < 16; i++)
#pragma unroll
        for (int r = 0; r < 4; r++) oacc[i][r] = 0.f;

    __syncthreads();

    for (int kb = 0; kb <= qb; kb++) {
        // ---- stage K hi/lo (64 x 192) and V^T hi/lo (128 x 64) ----
        {
            const __nv_bfloat16* ksh = kh_g + (bh * S_ + (size_t)kb * 64) * QKD_;
            const __nv_bfloat16* ksl = kl_g + (bh * S_ + (size_t)kb * 64) * QKD_;
            for (int idx = tid; idx < 64 * 24; idx += 128) {
                const int n = idx / 24, sg = idx - n * 24;
                *(uint4*)&Kh[n * QS + sg * 8] = *(const uint4*)(ksh + n * QKD_ + sg * 8);
                *(uint4*)&Kl[n * QS + sg * 8] = *(const uint4*)(ksl + n * QKD_ + sg * 8);
            }
            const __nv_bfloat16* vsh = vth_g + bh * VD_ * S_ + (size_t)kb * 64;
            const __nv_bfloat16* vsl = vtl_g + bh * VD_ * S_ + (size_t)kb * 64;
            for (int idx = tid; idx < 128 * 8; idx += 128) {
                const int d = idx >> 3, sg = idx & 7;
                *(uint4*)&Vh[d * VS + sg * 8] = *(const uint4*)(vsh + (size_t)d * S_ + sg * 8);
                *(uint4*)&Vl[d * VS + sg * 8] = *(const uint4*)(vsl + (size_t)d * S_ + sg * 8);
            }
        }
        __syncthreads();

        // ---- scores: sc[8 n-tiles][4], 3-term hi/lo ----
        float sc[8][4];
#pragma unroll
        for (int nt = 0; nt < 8; nt++)
#pragma unroll
            for (int r = 0; r < 4; r++) sc[nt][r] = 0.f;

#pragma unroll
        for (int ks = 0; ks < 12; ks++) {
            uint32_t ah[4], al4[4];
            ldsm_x4(ah[0], ah[1], ah[2], ah[3],   uQh + qbase + ks * 32);
            ldsm_x4(al4[0], al4[1], al4[2], al4[3], uQl + qbase + ks * 32);
            uint32_t kf[4][4], lf[4][4];
#pragma unroll
            for (int v = 0; v < 4; v++) {
                const uint32_t ka = krow + (uint32_t)(v * 16) * (QS * 2) + ks * 32;
                ldsm_x4(kf[v][0], kf[v][1], kf[v][2], kf[v][3], uKh + ka);
                ldsm_x4(lf[v][0], lf[v][1], lf[v][2], lf[v][3], uKl + ka);
            }
#pragma unroll
            for (int v = 0; v < 4; v++) {
                mma_16816(sc[2*v],   ah, kf[v][0], kf[v][1]);
                mma_16816(sc[2*v+1], ah, kf[v][2], kf[v][3]);
            }
#pragma unroll
            for (int v = 0; v < 4; v++) {
                mma_16816(sc[2*v],   ah, lf[v][0], lf[v][1]);
                mma_16816(sc[2*v+1], ah, lf[v][2], lf[v][3]);
            }
#pragma unroll
            for (int v = 0; v < 4; v++) {
                mma_16816(sc[2*v],   al4, kf[v][0], kf[v][1]);
                mma_16816(sc[2*v+1], al4, kf[v][2], kf[v][3]);
            }
        }

        // ---- scale + causal mask ----
#pragma unroll
        for (int nt = 0; nt < 8; nt++)
#pragma unroll
            for (int r = 0; r < 4; r++) sc[nt][r] *= scale;

        if (kb == qb) {
            const int r0 = m0 + g, r1 = r0 + 8;
#pragma unroll
            for (int nt = 0; nt < 8; nt++) {
                const int c = nt * 8 + 2 * t4;
                if (c     > r0) sc[nt][0] = -1e30f;
                if (c + 1 > r0) sc[nt][1] = -1e30f;
                if (c     > r1) sc[nt][2] = -1e30f;
                if (c + 1 > r1) sc[nt][3] = -1e30f;
            }
        }

        // ---- online softmax (rows g and g+8; quad = lanes sharing g) ----
        float mx0 = -1e30f, mx1 = -1e30f;
#pragma unroll
        for (int nt = 0; nt < 8; nt++) {
            mx0 = fmaxf(mx0, fmaxf(sc[nt][0], sc[nt][1]));
            mx1 = fmaxf(mx1, fmaxf(sc[nt][2], sc[nt][3]));
        }
        mx0 = fmaxf(mx0, __shfl_xor_sync(0xffffffffu, mx0, 1));
        mx0 = fmaxf(mx0, __shfl_xor_sync(0xffffffffu, mx0, 2));
        mx1 = fmaxf(mx1, __shfl_xor_sync(0xffffffffu, mx1, 1));
        mx1 = fmaxf(mx1, __shfl_xor_sync(0xffffffffu, mx1, 2));

        const float mn0 = fmaxf(m_i[0], mx0);
        const float mn1 = fmaxf(m_i[1], mx1);
        const float a0  = __expf(m_i[0] - mn0);
        const float a1  = __expf(m_i[1] - mn1);
        m_i[0] = mn0; m_i[1] = mn1;

        float rs0 = 0.f, rs1 = 0.f;
#pragma unroll
        for (int nt = 0; nt < 8; nt++) {
            sc[nt][0] = __expf(sc[nt][0] - mn0);
            sc[nt][1] = __expf(sc[nt][1] - mn0);
            sc[nt][2] = __expf(sc[nt][2] - mn1);
            sc[nt][3] = __expf(sc[nt][3] - mn1);
            rs0 += sc[nt][0] + sc[nt][1];
            rs1 += sc[nt][2] + sc[nt][3];
        }
        rs0 += __shfl_xor_sync(0xffffffffu, rs0, 1);
        rs0 += __shfl_xor_sync(0xffffffffu, rs0, 2);
        rs1 += __shfl_xor_sync(0xffffffffu, rs1, 1);
        rs1 += __shfl_xor_sync(0xffffffffu, rs1, 2);
        l_i[0] = l_i[0] * a0 + rs0;
        l_i[1] = l_i[1] * a1 + rs1;

#pragma unroll
        for (int dt = 0; dt < 16; dt++) {
            oacc[dt][0] *= a0; oacc[dt][1] *= a0;
            oacc[dt][2] *= a1; oacc[dt][3] *= a1;
        }

        // ---- PV: P register-resident A-fragments, V^T B-fragments, 3-term ----
#pragma unroll
        for (int kt = 0; kt < 4; kt++) {
            // P A-fragment for this k16: a0=(g, klow)=sc[2kt][0,1]; a1=(g+8, klow)=sc[2kt][2,3];
            // a2=(g, khigh)=sc[2kt+1][0,1]; a3=(g+8, khigh)=sc[2kt+1][2,3]
            uint32_t pa_h[4], pa_l[4];
#pragma unroll
            for (int j = 0; j < 4; j++) {
                const int nt = 2 * kt + (j >> 1);
                const int c0 = (j & 1) * 2;
                const float p0 = sc[nt][c0], p1 = sc[nt][c0 + 1];
                pa_h[j] = packbf(p0, p1);
                const float q0 = p0 - __bfloat162float(__float2bfloat16(p0));
                const float q1 = p1 - __bfloat162float(__float2bfloat16(p1));
                pa_l[j] = packbf(q0, q1);
            }
#pragma unroll
            for (int dp = 0; dp < 8; dp += 2) {
                uint32_t vh0[4], vl0[4], vh1[4], vl1[4];
                const uint32_t va0 = vrow + (uint32_t)(dp * 16) * (VS * 2) + kt * 32;
                const uint32_t va1 = va0 + 16u * (VS * 2);
                ldsm_x4(vh0[0], vh0[1], vh0[2], vh0[3], uVh + va0);
                ldsm_x4(vl0[0], vl0[1], vl0[2], vl0[3], uVl + va0);
                ldsm_x4(vh1[0], vh1[1], vh1[2], vh1[3], uVh + va1);
                ldsm_x4(vl1[0], vl1[1], vl1[2], vl1[3], uVl + va1);

                mma_16816(oacc[2*dp],   pa_h, vh0[0], vh0[1]);
                mma_16816(oacc[2*dp+1], pa_h, vh0[2], vh0[3]);
                mma_16816(oacc[2*dp+2], pa_h, vh1[0], vh1[1]);
                mma_16816(oacc[2*dp+3], pa_h, vh1[2], vh1[3]);

                mma_16816(oacc[2*dp],   pa_h, vl0[0], vl0[1]);
                mma_16816(oacc[2*dp+1], pa_h, vl0[2], vl0[3]);
                mma_16816(oacc[2*dp+2], pa_h, vl1[0], vl1[1]);
                mma_16816(oacc[2*dp+3], pa_h, vl1[2], vl1[3]);

                mma_16816(oacc[2*dp],   pa_l, vh0[0], vh0[1]);
                mma_16816(oacc[2*dp+1], pa_l, vh0[2], vh0[3]);
                mma_16816(oacc[2*dp+2], pa_l, vh1[0], vh1[1]);
                mma_16816(oacc[2*dp+3], pa_l, vh1[2], vh1[3]);
            }
        }
        __syncthreads();   // before next tile overwrites K/V smem
    }

    // ---- epilogue: divide by l, write hi/lo bf16 to (tok, h*128+d) ----
    const float inv0 = 1.f / l_i[0], inv1 = 1.f / l_i[1];
    const size_t row0 = (tok0 + m0 + g) * (size_t)(NH_ * VD_);
    const size_t row1 = row0 + 8 * (size_t)(NH_ * VD_);
#pragma unroll
    for (int dt = 0; dt < 16; dt++) {
        const int col = h * VD_ + dt * 8 + 2 * t4;
        const float o00 = oacc[dt][0] * inv0, o01 = oacc[dt][1] * inv0;
        const float o10 = oacc[dt][2] * inv1, o11 = oacc[dt][3] * inv1;
        *(uint32_t*)&oh[row0 + col] = packbf(o00, o01);
        *(uint32_t*)&oh[row1 + col] = packbf(o10, o11);
        const float r00 = o00 - __bfloat162float(__float2bfloat16(o00));
        const float r01 = o01 - __bfloat162float(__float2bfloat16(o01));
        const float r10 = o10 - __bfloat162float(__float2bfloat16(o10));
        const float r11 = o11 - __bfloat162float(__float2bfloat16(o11));
        *(uint32_t*)&ol[row0 + col] = packbf(r00, r01);
        *(uint32_t*)&ol[row1 + col] = packbf(r10, r11);
    }
}

// ============================================================================
// launch
// ============================================================================
extern "C" void kernel_launch(void* const* d_in, const int* in_sizes, int n_in,
                              void* d_out, int out_size)
{
    const float* x     = (const float*)d_in[0];
    const float* wq    = (const float*)d_in[1];
    const float* wkv_a = (const float*)d_in[2];
    const float* kvnw  = (const float*)d_in[3];
    const float* wkv_b = (const float*)d_in[4];
    const float* wo    = (const float*)d_in[5];
    const float* fc    = (const float*)d_in[6];
    const float* fs    = (const float*)d_in[7];
    float* out = (float*)d_out;

    float *q_p, *kv_p, *kpe_p, *kvb_p;
    __nv_bfloat16 *xh, *xl, *wqh, *wql, *wkvah, *wkval, *kvch, *kvcl;
    __nv_bfloat16 *wkvbh, *wkvbl, *atth, *attl, *woh, *wol;
    __nv_bfloat16 *kh, *kl, *vth, *vtl;
    cudaGetSymbolAddress((void**)&q_p,   g_q);
    cudaGetSymbolAddress((void**)&kv_p,  g_kv);
    cudaGetSymbolAddress((void**)&kpe_p, g_kpe);
    cudaGetSymbolAddress((void**)&kvb_p, g_kvb);
    cudaGetSymbolAddress((void**)&xh,    g_xh);
    cudaGetSymbolAddress((void**)&xl,    g_xl);
    cudaGetSymbolAddress((void**)&wqh,   g_wqh);
    cudaGetSymbolAddress((void**)&wql,   g_wql);
    cudaGetSymbolAddress((void**)&wkvah, g_wkvah);
    cudaGetSymbolAddress((void**)&wkval, g_wkval);
    cudaGetSymbolAddress((void**)&kvch,  g_kvch);
    cudaGetSymbolAddress((void**)&kvcl,  g_kvcl);
    cudaGetSymbolAddress((void**)&wkvbh, g_wkvbh);
    cudaGetSymbolAddress((void**)&wkvbl, g_wkvbl);
    cudaGetSymbolAddress((void**)&atth,  g_atth);
    cudaGetSymbolAddress((void**)&attl,  g_attl);
    cudaGetSymbolAddress((void**)&woh,   g_woh);
    cudaGetSymbolAddress((void**)&wol,   g_wol);
    cudaGetSymbolAddress((void**)&kh,    g_kh);
    cudaGetSymbolAddress((void**)&kl,    g_kl);
    cudaGetSymbolAddress((void**)&vth,   g_vth);
    cudaGetSymbolAddress((void**)&vtl,   g_vtl);

    // softmax scale with yarn mscale (MAX_LEN > ORIG_LEN)
    const double ms    = 0.1 * 1.0 * log(40.0) + 1.0;
    const float  scale = (float)(pow((double)QKD_, -0.5) * ms * ms);

    cudaFuncSetAttribute(flash_mma, cudaFuncAttributeMaxDynamicSharedMemorySize, FA2_SMEM);

    // 0. hi/lo decompositions of x and all weights
    {
        int n;
        n = NTOK_ * DIM_;                    cvt_hilo<<<(n + 255) / 256, 256>>>(x,     xh,    xl,    n);
        n = (NH_ * QKD_) * DIM_;             cvt_hilo<<<(n + 255) / 256, 256>>>(wq,    wqh,   wql,   n);
        n = (KVLORA_ + ROPE_) * DIM_;        cvt_hilo<<<(n + 255) / 256, 256>>>(wkv_a, wkvah, wkval, n);
        n = (NH_ * (NOPE_ + VD_)) * KVLORA_; cvt_hilo<<<(n + 255) / 256, 256>>>(wkv_b, wkvbh, wkvbl, n);
        n = DIM_ * (NH_ * VD_);              cvt_hilo<<<(n + 255) / 256, 256>>>(wo,    woh,   wol,   n);
    }

    // 1. q = x @ wq^T : (4096, 3072), K=2048
    bf3_gemm_mma<<<dim3((NH_ * QKD_ + 127) / 128, NTOK_ / 128), 256>>>(
        xh, xl, wqh, wql, q_p, NTOK_, NH_ * QKD_, DIM_);

    // 2. kv = x @ wkv_a^T : (4096, 576), K=2048
    bf3_gemm_mma<<<dim3((KVLORA_ + ROPE_ + 127) / 128, NTOK_ / 128), 256>>>(
        xh, xl, wkvah, wkval, kv_p, NTOK_, KVLORA_ + ROPE_, DIM_);

    // 3. RMSNorm kv_c (-> hi/lo) + RoPE k_pe
    kv_post_kernel<<<NTOK_, 128>>>(kv_p, kvnw, fc, fs, kvch, kvcl, kpe_p);

    // 4. kvb = kv_c_norm @ wkv_b^T : (4096, 4096), K=512
    bf3_gemm_mma<<<dim3((NH_ * (NOPE_ + VD_) + 127) / 128, NTOK_ / 128), 256>>>(
        kvch, kvcl, wkvbh, wkvbl, kvb_p, NTOK_, NH_ * (NOPE_ + VD_), KVLORA_);

    // 5. attention operand prep: K hi/lo (b,h,s,192), V^T hi/lo (b,h,d,s)
    {
        const int n = B_ * NH_ * S_ * QKD_;
        prep_k<<<(n + 255) / 256, 256>>>(kvb_p, kpe_p, kh, kl);
        prep_vt<<<dim3(S_ / 64, VD_ / 64, B_ * NH_), 256>>>(kvb_p, vth, vtl);
    }

    // 6. tensor-core causal flash attention (-> hi/lo bf16)
    flash_mma<<<dim3(S_ / 64, NH_, B_), 128, FA2_SMEM>>>(
        q_p, kh, kl, vth, vtl, atth, attl, scale);

    // 7. out = attn @ wo^T : (4096, 2048), K=2048
    bf3_gemm_mma<<<dim3((DIM_ + 127) / 128, NTOK_ / 128), 256>>>(
        atth, attl, woh, wol, out, NTOK_, DIM_, NH_ * VD_);
}

// round 17
// speedup vs baseline: 3.1527x; 1.0155x over previous
#include <cuda_runtime.h>
#include <cuda_bf16.h>
#include <math.h>
#include <cstdint>

// ---------------- problem constants ----------------
#define B_       2
#define S_       2048
#define DIM_     2048
#define NH_      16
#define QKD_     192     // NOPE(128) + ROPE(64)
#define NOPE_    128
#define ROPE_    64
#define VD_      128
#define KVLORA_  512
#define NTOK_    (B_ * S_)   // 4096

// ---------------- scratch (static device globals; no allocation) ----------------
__device__ float g_q   [NTOK_ * (NH_ * QKD_)];          // fp32 q (tok, head, 192)
__device__ float g_kv  [NTOK_ * (KVLORA_ + ROPE_)];
__device__ float g_kpe [NTOK_ * ROPE_];
__device__ float g_kvb [NTOK_ * (NH_ * (NOPE_ + VD_))]; // fp32 (tok, head, 256)

// hi/lo bf16 decompositions (3xBF16 GEMM operands)
__device__ __nv_bfloat16 g_xh   [NTOK_ * DIM_];
__device__ __nv_bfloat16 g_xl   [NTOK_ * DIM_];
__device__ __nv_bfloat16 g_wqh  [(NH_ * QKD_) * DIM_];
__device__ __nv_bfloat16 g_wql  [(NH_ * QKD_) * DIM_];
__device__ __nv_bfloat16 g_wkvah[(KVLORA_ + ROPE_) * DIM_];
__device__ __nv_bfloat16 g_wkval[(KVLORA_ + ROPE_) * DIM_];
__device__ __nv_bfloat16 g_kvch [NTOK_ * KVLORA_];
__device__ __nv_bfloat16 g_kvcl [NTOK_ * KVLORA_];
__device__ __nv_bfloat16 g_wkvbh[(NH_ * (NOPE_ + VD_)) * KVLORA_];
__device__ __nv_bfloat16 g_wkvbl[(NH_ * (NOPE_ + VD_)) * KVLORA_];
__device__ __nv_bfloat16 g_atth [NTOK_ * (NH_ * VD_)];
__device__ __nv_bfloat16 g_attl [NTOK_ * (NH_ * VD_)];
__device__ __nv_bfloat16 g_woh  [DIM_ * (NH_ * VD_)];
__device__ __nv_bfloat16 g_wol  [DIM_ * (NH_ * VD_)];

// flash-attention bf16 operands: K (b,h,s,192) and V^T (b,h,d,s)
__device__ __nv_bfloat16 g_kh  [B_ * NH_ * S_ * QKD_];
__device__ __nv_bfloat16 g_kl  [B_ * NH_ * S_ * QKD_];
__device__ __nv_bfloat16 g_vth [B_ * NH_ * VD_ * S_];
__device__ __nv_bfloat16 g_vtl [B_ * NH_ * VD_ * S_];

// ============================================================================
// Warp-MMA helpers (portable PTX: works on compute_103 generic target)
// ============================================================================
__device__ __forceinline__ uint32_t smem_u32(const void* p) {
    uint32_t a;
    asm("{ .reg .u64 t; cvta.to.shared.u64 t, %1; cvt.u32.u64 %0, t; }"
        : "=r"(a) : "l"(p));
    return a;
}

__device__ __forceinline__ void ldsm_x4(uint32_t& r0, uint32_t& r1,
                                        uint32_t& r2, uint32_t& r3, uint32_t addr) {
    asm volatile("ldmatrix.sync.aligned.m8n8.x4.shared.b16 {%0,%1,%2,%3}, [%4];"
                 : "=r"(r0), "=r"(r1), "=r"(r2), "=r"(r3) : "r"(addr));
}

__device__ __forceinline__ void mma_16816(float* d, const uint32_t* a,
                                          uint32_t b0, uint32_t b1) {
    asm volatile(
        "mma.sync.aligned.m16n8k16.row.col.f32.bf16.bf16.f32 "
        "{%0,%1,%2,%3}, {%4,%5,%6,%7}, {%8,%9}, {%0,%1,%2,%3};"
        : "+f"(d[0]), "+f"(d[1]), "+f"(d[2]), "+f"(d[3])
        : "r"(a[0]), "r"(a[1]), "r"(a[2]), "r"(a[3]), "r"(b0), "r"(b1));
}

__device__ __forceinline__ uint32_t packbf(float lo, float hi) {
    uint32_t r;
    asm("cvt.rn.bf16x2.f32 %0, %1, %2;" : "=r"(r) : "f"(hi), "f"(lo));
    return r;
}

// cp.async 16B (portable since sm_80; compiles on compute_103)
__device__ __forceinline__ void cp_async16(uint32_t dst, const void* src) {
    asm volatile("cp.async.cg.shared.global [%0], [%1], 16;"
                 :: "r"(dst), "l"(src));
}
#define CP_COMMIT() asm volatile("cp.async.commit_group;" ::: "memory")
#define CP_WAIT0()  asm volatile("cp.async.wait_group 0;" ::: "memory")

// ============================================================================
// 3xBF16 tensor-core GEMM, cp.async double-buffered:
//   C[M,N] = (Ah+Al)[M,K] * (Bh+Bl)[N,K]^T   (fp32 accumulate)
// CTA tile 128x128, K chunk 32, 256 threads = 8 warps (2x4), warp tile 64x32.
// SMEM: 2 stages x 4 tiles x [128][40] bf16 (80B stride, conflict-free ldmatrix).
// ============================================================================
#define GST      40
#define GTILE_E  (128 * GST)        // bf16 elems per tile
#define GSTAGE_E (4 * GTILE_E)      // per stage
#define GSMEM_B  (2 * GSTAGE_E * 2) // bytes total (81920)

// issue one stage's 4 tiles via cp.async (8 x 16B per thread)
__device__ __forceinline__ void cp_stage(uint32_t stg_base,
                                         const __nv_bfloat16* __restrict__ Ah,
                                         const __nv_bfloat16* __restrict__ Al,
                                         const __nv_bfloat16* __restrict__ Bh,
                                         const __nv_bfloat16* __restrict__ Bl,
                                         int bm, int bn, int M, int N, int K,
                                         int k0, int tid)
{
    const __nv_bfloat16* srcs[4] = {Ah, Al, Bh, Bl};
    const int r0s[2] = {bm, bn};
    const int nrs[2] = {M, N};
#pragma unroll
    for (int tl = 0; tl < 4; tl++) {
        const int r0 = r0s[tl >> 1];
        const int nr = nrs[tl >> 1];
        const uint32_t tb = stg_base + (uint32_t)tl * (GTILE_E * 2);
#pragma unroll
        for (int i = 0; i < 2; i++) {
            const int u = tid + i * 256;           // 0..511
            const int r = u >> 2;                  // row 0..127
            const int s4 = u & 3;                  // 16B segment
            // clamp OOB rows to last valid row: epilogue guards gc<N, so the
            // garbage columns are computed but never stored.
            int gr = r0 + r; if (gr > nr - 1) gr = nr - 1;
            cp_async16(tb + (uint32_t)(r * (GST * 2) + s4 * 16),
                       srcs[tl] + (size_t)gr * K + k0 + s4 * 8);
        }
    }
    CP_COMMIT();
}

__global__ __launch_bounds__(256, 2)
void bf3_gemm_mma(const __nv_bfloat16* __restrict__ Ah, const __nv_bfloat16* __restrict__ Al,
                  const __nv_bfloat16* __restrict__ Bh, const __nv_bfloat16* __restrict__ Bl,
                  float* __restrict__ C, int M, int N, int K)
{
    extern __shared__ __nv_bfloat16 smp[];   // 2 stages x 4 tiles x 128 x GST

    const int tid   = threadIdx.x;
    const int wid   = tid >> 5;
    const int lane  = tid & 31;
    const int wm    = wid & 1;
    const int wn    = wid >> 1;
    const int bm    = blockIdx.y * 128;
    const int bn    = blockIdx.x * 128;

    const uint32_t sb = smem_u32(smp);

    const int mat = lane >> 3, rr = lane & 7;
    uint32_t aoff[4];
#pragma unroll
    for (int mt = 0; mt < 4; mt++) {
        const int row = wm * 64 + mt * 16 + rr + (mat & 1) * 8;
        aoff[mt] = row * (GST * 2) + (mat >> 1) * 16;
    }
    uint32_t boff[2];
#pragma unroll
    for (int v = 0; v < 2; v++) {
        const int row = wn * 32 + v * 16 + rr + (mat >> 1) * 8;
        boff[v] = row * (GST * 2) + (mat & 1) * 16;
    }

    float acc[4][4][4];
#pragma unroll
    for (int i = 0; i < 4; i++)
#pragma unroll
        for (int j = 0; j < 4; j++)
#pragma unroll
            for (int r = 0; r < 4; r++) acc[i][j][r] = 0.f;

    const int NC = K >> 5;   // chunks of 32

    // prologue: stage 0
    cp_stage(sb, Ah, Al, Bh, Bl, bm, bn, M, N, K, 0, tid);

    for (int c = 0; c < NC; c++) {
        const uint32_t stg = sb + (uint32_t)(c & 1) * (GSTAGE_E * 2);

        CP_WAIT0();            // stage c data arrived
        __syncthreads();       // all warps done with the buffer we're about to refill

        if (c + 1 < NC) {      // prefetch next chunk into the other buffer (async)
            cp_stage(sb + (uint32_t)((c + 1) & 1) * (GSTAGE_E * 2),
                     Ah, Al, Bh, Bl, bm, bn, M, N, K, (c + 1) << 5, tid);
        }

        const uint32_t tAh = stg;
        const uint32_t tAl = stg + 1 * (GTILE_E * 2);
        const uint32_t tBh = stg + 2 * (GTILE_E * 2);
        const uint32_t tBl = stg + 3 * (GTILE_E * 2);

#pragma unroll
        for (int ks = 0; ks < 2; ks++) {
            const uint32_t kc = ks * 32;
            uint32_t af[4][4], bh[4][2], bl[4][2];
#pragma unroll
            for (int mt = 0; mt < 4; mt++)
                ldsm_x4(af[mt][0], af[mt][1], af[mt][2], af[mt][3], tAh + aoff[mt] + kc);
#pragma unroll
            for (int v = 0; v < 2; v++) {
                ldsm_x4(bh[v*2][0], bh[v*2][1], bh[v*2+1][0], bh[v*2+1][1], tBh + boff[v] + kc);
                ldsm_x4(bl[v*2][0], bl[v*2][1], bl[v*2+1][0], bl[v*2+1][1], tBl + boff[v] + kc);
            }
#pragma unroll
            for (int mt = 0; mt < 4; mt++)
#pragma unroll
                for (int nt = 0; nt < 4; nt++)
                    mma_16816(acc[mt][nt], af[mt], bh[nt][0], bh[nt][1]);
#pragma unroll
            for (int mt = 0; mt < 4; mt++)
#pragma unroll
                for (int nt = 0; nt < 4; nt++)
                    mma_16816(acc[mt][nt], af[mt], bl[nt][0], bl[nt][1]);
#pragma unroll
            for (int mt = 0; mt < 4; mt++)
                ldsm_x4(af[mt][0], af[mt][1], af[mt][2], af[mt][3], tAl + aoff[mt] + kc);
#pragma unroll
            for (int mt = 0; mt < 4; mt++)
#pragma unroll
                for (int nt = 0; nt < 4; nt++)
                    mma_16816(acc[mt][nt], af[mt], bh[nt][0], bh[nt][1]);
        }
        __syncthreads();   // done reading stage c before it is refilled (iteration c+2)
    }

    const int g = lane >> 2, t = lane & 3;
#pragma unroll
    for (int mt = 0; mt < 4; mt++) {
        const int gm = bm + wm * 64 + mt * 16 + g;
#pragma unroll
        for (int nt = 0; nt < 4; nt++) {
            const int gc = bn + wn * 32 + nt * 8 + 2 * t;
            if (gc < N) {
                *(float2*)(C + (size_t)gm * N + gc) =
                    make_float2(acc[mt][nt][0], acc[mt][nt][1]);
                *(float2*)(C + (size_t)(gm + 8) * N + gc) =
                    make_float2(acc[mt][nt][2], acc[mt][nt][3]);
            }
        }
    }
}

// ============================================================================
// fp32 -> (hi, lo) bf16 decomposition
// ============================================================================
__global__ void cvt_hilo(const float* __restrict__ x,
                         __nv_bfloat16* __restrict__ h,
                         __nv_bfloat16* __restrict__ l, int n)
{
    const int i = blockIdx.x * 256 + threadIdx.x;
    if (i < n) {
        const float v = x[i];
        const __nv_bfloat16 hv = __float2bfloat16(v);
        h[i] = hv;
        l[i] = __float2bfloat16(v - __bfloat162float(hv));
    }
}

// ============================================================================
// Per-token: RMSNorm(kv_c) -> hi/lo bf16 ; RoPE(k_pe) -> g_kpe.
// (reference applies RoPE only to k_pe; q stays un-rotated)
// ============================================================================
__global__ __launch_bounds__(128) void kv_post_kernel(
    const float* __restrict__ kv, const float* __restrict__ kvnw,
    const float* __restrict__ fc, const float* __restrict__ fs,
    __nv_bfloat16* __restrict__ kvch, __nv_bfloat16* __restrict__ kvcl,
    float* __restrict__ kpe)
{
    const int tok = blockIdx.x;
    const int s   = tok & (S_ - 1);
    const float* row = kv + (size_t)tok * (KVLORA_ + ROPE_);

    __shared__ float red[4];
    float ss = 0.f;
    for (int d = threadIdx.x; d < KVLORA_; d += 128) {
        const float v = row[d];
        ss += v * v;
    }
#pragma unroll
    for (int off = 16; off; off >>= 1) ss += __shfl_xor_sync(0xffffffffu, ss, off);
    if ((threadIdx.x & 31) == 0) red[threadIdx.x >> 5] = ss;
    __syncthreads();
    const float tot = red[0] + red[1] + red[2] + red[3];
    const float rn  = rsqrtf(tot / (float)KVLORA_ + 1e-6f);

    for (int d = threadIdx.x; d < KVLORA_; d += 128) {
        const float y = row[d] * rn * kvnw[d];
        const __nv_bfloat16 hv = __float2bfloat16(y);
        kvch[(size_t)tok * KVLORA_ + d] = hv;
        kvcl[(size_t)tok * KVLORA_ + d] = __float2bfloat16(y - __bfloat162float(hv));
    }

    if (threadIdx.x < 32) {
        const int p  = threadIdx.x;
        const float xr = row[KVLORA_ + 2 * p];
        const float xi = row[KVLORA_ + 2 * p + 1];
        const float c  = fc[s * 32 + p];
        const float sn = fs[s * 32 + p];
        kpe[(size_t)tok * ROPE_ + 2 * p]     = xr * c - xi * sn;
        kpe[(size_t)tok * ROPE_ + 2 * p + 1] = xr * sn + xi * c;
    }
}

// ============================================================================
// prep_k: build K = [k_nope | k_pe] hi/lo bf16, layout (b, h, s, 192)
// ============================================================================
__global__ void prep_k(const float* __restrict__ kvb, const float* __restrict__ kpe,
                       __nv_bfloat16* __restrict__ kh, __nv_bfloat16* __restrict__ kl)
{
    const int i = blockIdx.x * 256 + threadIdx.x;
    const int total = B_ * NH_ * S_ * QKD_;
    if (i >= total) return;
    const int d  = i % QKD_;
    const int sr = i / QKD_;
    const int s  = sr & (S_ - 1);
    const int bh = sr >> 11;
    const int b  = bh >> 4, h = bh & 15;
    const int tok = b * S_ + s;
    float v;
    if (d < NOPE_) v = kvb[((size_t)tok * NH_ + h) * (NOPE_ + VD_) + d];
    else           v = kpe[(size_t)tok * ROPE_ + d - NOPE_];
    const __nv_bfloat16 hv = __float2bfloat16(v);
    kh[i] = hv;
    kl[i] = __float2bfloat16(v - __bfloat162float(hv));
}

// ============================================================================
// prep_vt: V^T hi/lo bf16, layout (b, h, d, s). Tile transpose via smem.
// ============================================================================
__global__ __launch_bounds__(256) void prep_vt(const float* __restrict__ kvb,
                                               __nv_bfloat16* __restrict__ vth,
                                               __nv_bfloat16* __restrict__ vtl)
{
    __shared__ float tile[64][65];
    const int st = blockIdx.x, dt = blockIdx.y, bh = blockIdx.z;
    const int b = bh >> 4, h = bh & 15;
    const int tid = threadIdx.x;

#pragma unroll
    for (int k = 0; k < 16; k++) {
        const int idx = tid + k * 256;
        const int i = idx >> 6, j = idx & 63;
        const int tok = b * S_ + st * 64 + i;
        tile[i][j] = kvb[((size_t)tok * NH_ + h) * (NOPE_ + VD_) + NOPE_ + dt * 64 + j];
    }
    __syncthreads();
#pragma unroll
    for (int k = 0; k < 16; k++) {
        const int idx = tid + k * 256;
        const int j = idx >> 6, i = idx & 63;
        const float v = tile[i][j];
        const __nv_bfloat16 hv = __float2bfloat16(v);
        const size_t o = ((size_t)bh * VD_ + dt * 64 + j) * S_ + st * 64 + i;
        vth[o] = hv;
        vtl[o] = __float2bfloat16(v - __bfloat162float(hv));
    }
}

// ============================================================================
// Tensor-core causal flash attention (3xBF16 QK and PV, fp32 softmax).
// grid = (S/64, NH, B), 128 threads = 4 warps, warp owns 16 query rows.
// ============================================================================
#define QS 200
#define VS 72
#define FA2_SMEM ((4 * 64 * QS + 2 * 128 * VS) * 2)

__global__ __launch_bounds__(128) void flash_mma(
    const float* __restrict__ q,
    const __nv_bfloat16* __restrict__ kh_g, const __nv_bfloat16* __restrict__ kl_g,
    const __nv_bfloat16* __restrict__ vth_g, const __nv_bfloat16* __restrict__ vtl_g,
    __nv_bfloat16* __restrict__ oh, __nv_bfloat16* __restrict__ ol,
    float scale)
{
    extern __shared__ __nv_bfloat16 sbm[];
    __nv_bfloat16* Qh = sbm;
    __nv_bfloat16* Ql = sbm + 64 * QS;
    __nv_bfloat16* Kh = sbm + 2 * 64 * QS;
    __nv_bfloat16* Kl = sbm + 3 * 64 * QS;
    __nv_bfloat16* Vh = sbm + 4 * 64 * QS;
    __nv_bfloat16* Vl = sbm + 4 * 64 * QS + 128 * VS;

    const int qb = blockIdx.x, h = blockIdx.y, b = blockIdx.z;
    const int tid = threadIdx.x, wid = tid >> 5, lane = tid & 31;
    const int g = lane >> 2, t4 = lane & 3;
    const int mat = lane >> 3, rr = lane & 7;
    const int m0 = wid * 16;
    const size_t tok0 = (size_t)b * S_ + (size_t)qb * 64;
    const size_t bh   = (size_t)b * NH_ + h;

    const uint32_t uQh = smem_u32(Qh), uQl = smem_u32(Ql);
    const uint32_t uKh = smem_u32(Kh), uKl = smem_u32(Kl);
    const uint32_t uVh = smem_u32(Vh), uVl = smem_u32(Vl);

    const uint32_t qbase = (uint32_t)((m0 + rr + (mat & 1) * 8) * (QS * 2) + (mat >> 1) * 16);
    const uint32_t krow  = (uint32_t)((rr + (mat >> 1) * 8) * (QS * 2) + (mat & 1) * 16);
    const uint32_t vrow  = (uint32_t)((rr + (mat >> 1) * 8) * (VS * 2) + (mat & 1) * 16);

    for (int idx = tid; idx < 64 * 48; idx += 128) {
        const int m = idx / 48, seg = idx - m * 48;
        const float4 v = *(const float4*)(q + ((tok0 + m) * NH_ + h) * QKD_ + seg * 4);
        const uint32_t h01 = packbf(v.x, v.y);
        const uint32_t h23 = packbf(v.z, v.w);
        const float r0 = v.x - __bfloat162float(__float2bfloat16(v.x));
        const float r1 = v.y - __bfloat162float(__float2bfloat16(v.y));
        const float r2 = v.z - __bfloat162float(__float2bfloat16(v.z));
        const float r3 = v.w - __bfloat162float(__float2bfloat16(v.w));
        *(uint32_t*)&Qh[m * QS + seg * 4]     = h01;
        *(uint32_t*)&Qh[m * QS + seg * 4 + 2] = h23;
        *(uint32_t*)&Ql[m * QS + seg * 4]     = packbf(r0, r1);
        *(uint32_t*)&Ql[m * QS + seg * 4 + 2] = packbf(r2, r3);
    }

    float m_i[2] = {-1e30f, -1e30f}, l_i[2] = {0.f, 0.f};
    float oacc[16][4];
#pragma unroll
    for (int i = 0; i < 16; i++)
#pragma unroll
        for (int r = 0; r < 4; r++) oacc[i][r] = 0.f;

    __syncthreads();

    for (int kb = 0; kb <= qb; kb++) {
        {
            const __nv_bfloat16* ksh = kh_g + (bh * S_ + (size_t)kb * 64) * QKD_;
            const __nv_bfloat16* ksl = kl_g + (bh * S_ + (size_t)kb * 64) * QKD_;
            for (int idx = tid; idx < 64 * 24; idx += 128) {
                const int n = idx / 24, sg = idx - n * 24;
                *(uint4*)&Kh[n * QS + sg * 8] = *(const uint4*)(ksh + n * QKD_ + sg * 8);
                *(uint4*)&Kl[n * QS + sg * 8] = *(const uint4*)(ksl + n * QKD_ + sg * 8);
            }
            const __nv_bfloat16* vsh = vth_g + bh * VD_ * S_ + (size_t)kb * 64;
            const __nv_bfloat16* vsl = vtl_g + bh * VD_ * S_ + (size_t)kb * 64;
            for (int idx = tid; idx < 128 * 8; idx += 128) {
                const int d = idx >> 3, sg = idx & 7;
                *(uint4*)&Vh[d * VS + sg * 8] = *(const uint4*)(vsh + (size_t)d * S_ + sg * 8);
                *(uint4*)&Vl[d * VS + sg * 8] = *(const uint4*)(vsl + (size_t)d * S_ + sg * 8);
            }
        }
        __syncthreads();

        float sc[8][4];
#pragma unroll
        for (int nt = 0; nt < 8; nt++)
#pragma unroll
            for (int r = 0; r < 4; r++) sc[nt][r] = 0.f;

#pragma unroll
        for (int ks = 0; ks < 12; ks++) {
            uint32_t ah[4], al4[4];
            ldsm_x4(ah[0], ah[1], ah[2], ah[3],   uQh + qbase + ks * 32);
            ldsm_x4(al4[0], al4[1], al4[2], al4[3], uQl + qbase + ks * 32);
            uint32_t kf[4][4], lf[4][4];
#pragma unroll
            for (int v = 0; v < 4; v++) {
                const uint32_t ka = krow + (uint32_t)(v * 16) * (QS * 2) + ks * 32;
                ldsm_x4(kf[v][0], kf[v][1], kf[v][2], kf[v][3], uKh + ka);
                ldsm_x4(lf[v][0], lf[v][1], lf[v][2], lf[v][3], uKl + ka);
            }
#pragma unroll
            for (int v = 0; v < 4; v++) {
                mma_16816(sc[2*v],   ah, kf[v][0], kf[v][1]);
                mma_16816(sc[2*v+1], ah, kf[v][2], kf[v][3]);
            }
#pragma unroll
            for (int v = 0; v < 4; v++) {
                mma_16816(sc[2*v],   ah, lf[v][0], lf[v][1]);
                mma_16816(sc[2*v+1], ah, lf[v][2], lf[v][3]);
            }
#pragma unroll
            for (int v = 0; v < 4; v++) {
                mma_16816(sc[2*v],   al4, kf[v][0], kf[v][1]);
                mma_16816(sc[2*v+1], al4, kf[v][2], kf[v][3]);
            }
        }

#pragma unroll
        for (int nt = 0; nt < 8; nt++)
#pragma unroll
            for (int r = 0; r < 4; r++) sc[nt][r] *= scale;

        if (kb == qb) {
            const int r0 = m0 + g, r1 = r0 + 8;
#pragma unroll
            for (int nt = 0; nt < 8; nt++) {
                const int c = nt * 8 + 2 * t4;
                if (c     > r0) sc[nt][0] = -1e30f;
                if (c + 1 > r0) sc[nt][1] = -1e30f;
                if (c     > r1) sc[nt][2] = -1e30f;
                if (c + 1 > r1) sc[nt][3] = -1e30f;
            }
        }

        float mx0 = -1e30f, mx1 = -1e30f;
#pragma unroll
        for (int nt = 0; nt < 8; nt++) {
            mx0 = fmaxf(mx0, fmaxf(sc[nt][0], sc[nt][1]));
            mx1 = fmaxf(mx1, fmaxf(sc[nt][2], sc[nt][3]));
        }
        mx0 = fmaxf(mx0, __shfl_xor_sync(0xffffffffu, mx0, 1));
        mx0 = fmaxf(mx0, __shfl_xor_sync(0xffffffffu, mx0, 2));
        mx1 = fmaxf(mx1, __shfl_xor_sync(0xffffffffu, mx1, 1));
        mx1 = fmaxf(mx1, __shfl_xor_sync(0xffffffffu, mx1, 2));

        const float mn0 = fmaxf(m_i[0], mx0);
        const float mn1 = fmaxf(m_i[1], mx1);
        const float a0  = __expf(m_i[0] - mn0);
        const float a1  = __expf(m_i[1] - mn1);
        m_i[0] = mn0; m_i[1] = mn1;

        float rs0 = 0.f, rs1 = 0.f;
#pragma unroll
        for (int nt = 0; nt < 8; nt++) {
            sc[nt][0] = __expf(sc[nt][0] - mn0);
            sc[nt][1] = __expf(sc[nt][1] - mn0);
            sc[nt][2] = __expf(sc[nt][2] - mn1);
            sc[nt][3] = __expf(sc[nt][3] - mn1);
            rs0 += sc[nt][0] + sc[nt][1];
            rs1 += sc[nt][2] + sc[nt][3];
        }
        rs0 += __shfl_xor_sync(0xffffffffu, rs0, 1);
        rs0 += __shfl_xor_sync(0xffffffffu, rs0, 2);
        rs1 += __shfl_xor_sync(0xffffffffu, rs1, 1);
        rs1 += __shfl_xor_sync(0xffffffffu, rs1, 2);
        l_i[0] = l_i[0] * a0 + rs0;
        l_i[1] = l_i[1] * a1 + rs1;

#pragma unroll
        for (int dt = 0; dt < 16; dt++) {
            oacc[dt][0] *= a0; oacc[dt][1] *= a0;
            oacc[dt][2] *= a1; oacc[dt][3] *= a1;
        }

#pragma unroll
        for (int kt = 0; kt < 4; kt++) {
            uint32_t pa_h[4], pa_l[4];
#pragma unroll
            for (int j = 0; j < 4; j++) {
                const int nt = 2 * kt + (j >> 1);
                const int c0 = (j & 1) * 2;
                const float p0 = sc[nt][c0], p1 = sc[nt][c0 + 1];
                pa_h[j] = packbf(p0, p1);
                const float q0 = p0 - __bfloat162float(__float2bfloat16(p0));
                const float q1 = p1 - __bfloat162float(__float2bfloat16(p1));
                pa_l[j] = packbf(q0, q1);
            }
#pragma unroll
            for (int dp = 0; dp < 8; dp += 2) {
                uint32_t vh0[4], vl0[4], vh1[4], vl1[4];
                const uint32_t va0 = vrow + (uint32_t)(dp * 16) * (VS * 2) + kt * 32;
                const uint32_t va1 = va0 + 16u * (VS * 2);
                ldsm_x4(vh0[0], vh0[1], vh0[2], vh0[3], uVh + va0);
                ldsm_x4(vl0[0], vl0[1], vl0[2], vl0[3], uVl + va0);
                ldsm_x4(vh1[0], vh1[1], vh1[2], vh1[3], uVh + va1);
                ldsm_x4(vl1[0], vl1[1], vl1[2], vl1[3], uVl + va1);

                mma_16816(oacc[2*dp],   pa_h, vh0[0], vh0[1]);
                mma_16816(oacc[2*dp+1], pa_h, vh0[2], vh0[3]);
                mma_16816(oacc[2*dp+2], pa_h, vh1[0], vh1[1]);
                mma_16816(oacc[2*dp+3], pa_h, vh1[2], vh1[3]);

                mma_16816(oacc[2*dp],   pa_h, vl0[0], vl0[1]);
                mma_16816(oacc[2*dp+1], pa_h, vl0[2], vl0[3]);
                mma_16816(oacc[2*dp+2], pa_h, vl1[0], vl1[1]);
                mma_16816(oacc[2*dp+3], pa_h, vl1[2], vl1[3]);

                mma_16816(oacc[2*dp],   pa_l, vh0[0], vh0[1]);
                mma_16816(oacc[2*dp+1], pa_l, vh0[2], vh0[3]);
                mma_16816(oacc[2*dp+2], pa_l, vh1[0], vh1[1]);
                mma_16816(oacc[2*dp+3], pa_l, vh1[2], vh1[3]);
            }
        }
        __syncthreads();
    }

    const float inv0 = 1.f / l_i[0], inv1 = 1.f / l_i[1];
    const size_t row0 = (tok0 + m0 + g) * (size_t)(NH_ * VD_);
    const size_t row1 = row0 + 8 * (size_t)(NH_ * VD_);
#pragma unroll
    for (int dt = 0; dt < 16; dt++) {
        const int col = h * VD_ + dt * 8 + 2 * t4;
        const float o00 = oacc[dt][0] * inv0, o01 = oacc[dt][1] * inv0;
        const float o10 = oacc[dt][2] * inv1, o11 = oacc[dt][3] * inv1;
        *(uint32_t*)&oh[row0 + col] = packbf(o00, o01);
        *(uint32_t*)&oh[row1 + col] = packbf(o10, o11);
        const float r00 = o00 - __bfloat162float(__float2bfloat16(o00));
        const float r01 = o01 - __bfloat162float(__float2bfloat16(o01));
        const float r10 = o10 - __bfloat162float(__float2bfloat16(o10));
        const float r11 = o11 - __bfloat162float(__float2bfloat16(o11));
        *(uint32_t*)&ol[row0 + col] = packbf(r00, r01);
        *(uint32_t*)&ol[row1 + col] = packbf(r10, r11);
    }
}

// ============================================================================
// launch
// ============================================================================
extern "C" void kernel_launch(void* const* d_in, const int* in_sizes, int n_in,
                              void* d_out, int out_size)
{
    const float* x     = (const float*)d_in[0];
    const float* wq    = (const float*)d_in[1];
    const float* wkv_a = (const float*)d_in[2];
    const float* kvnw  = (const float*)d_in[3];
    const float* wkv_b = (const float*)d_in[4];
    const float* wo    = (const float*)d_in[5];
    const float* fc    = (const float*)d_in[6];
    const float* fs    = (const float*)d_in[7];
    float* out = (float*)d_out;

    float *q_p, *kv_p, *kpe_p, *kvb_p;
    __nv_bfloat16 *xh, *xl, *wqh, *wql, *wkvah, *wkval, *kvch, *kvcl;
    __nv_bfloat16 *wkvbh, *wkvbl, *atth, *attl, *woh, *wol;
    __nv_bfloat16 *kh, *kl, *vth, *vtl;
    cudaGetSymbolAddress((void**)&q_p,   g_q);
    cudaGetSymbolAddress((void**)&kv_p,  g_kv);
    cudaGetSymbolAddress((void**)&kpe_p, g_kpe);
    cudaGetSymbolAddress((void**)&kvb_p, g_kvb);
    cudaGetSymbolAddress((void**)&xh,    g_xh);
    cudaGetSymbolAddress((void**)&xl,    g_xl);
    cudaGetSymbolAddress((void**)&wqh,   g_wqh);
    cudaGetSymbolAddress((void**)&wql,   g_wql);
    cudaGetSymbolAddress((void**)&wkvah, g_wkvah);
    cudaGetSymbolAddress((void**)&wkval, g_wkval);
    cudaGetSymbolAddress((void**)&kvch,  g_kvch);
    cudaGetSymbolAddress((void**)&kvcl,  g_kvcl);
    cudaGetSymbolAddress((void**)&wkvbh, g_wkvbh);
    cudaGetSymbolAddress((void**)&wkvbl, g_wkvbl);
    cudaGetSymbolAddress((void**)&atth,  g_atth);
    cudaGetSymbolAddress((void**)&attl,  g_attl);
    cudaGetSymbolAddress((void**)&woh,   g_woh);
    cudaGetSymbolAddress((void**)&wol,   g_wol);
    cudaGetSymbolAddress((void**)&kh,    g_kh);
    cudaGetSymbolAddress((void**)&kl,    g_kl);
    cudaGetSymbolAddress((void**)&vth,   g_vth);
    cudaGetSymbolAddress((void**)&vtl,   g_vtl);

    // softmax scale with yarn mscale (MAX_LEN > ORIG_LEN)
    const double ms    = 0.1 * 1.0 * log(40.0) + 1.0;
    const float  scale = (float)(pow((double)QKD_, -0.5) * ms * ms);

    cudaFuncSetAttribute(bf3_gemm_mma, cudaFuncAttributeMaxDynamicSharedMemorySize, GSMEM_B);
    cudaFuncSetAttribute(flash_mma, cudaFuncAttributeMaxDynamicSharedMemorySize, FA2_SMEM);

    // 0. hi/lo decompositions of x and all weights
    {
        int n;
        n = NTOK_ * DIM_;                    cvt_hilo<<<(n + 255) / 256, 256>>>(x,     xh,    xl,    n);
        n = (NH_ * QKD_) * DIM_;             cvt_hilo<<<(n + 255) / 256, 256>>>(wq,    wqh,   wql,   n);
        n = (KVLORA_ + ROPE_) * DIM_;        cvt_hilo<<<(n + 255) / 256, 256>>>(wkv_a, wkvah, wkval, n);
        n = (NH_ * (NOPE_ + VD_)) * KVLORA_; cvt_hilo<<<(n + 255) / 256, 256>>>(wkv_b, wkvbh, wkvbl, n);
        n = DIM_ * (NH_ * VD_);              cvt_hilo<<<(n + 255) / 256, 256>>>(wo,    woh,   wol,   n);
    }

    // 1. q = x @ wq^T : (4096, 3072), K=2048
    bf3_gemm_mma<<<dim3((NH_ * QKD_ + 127) / 128, NTOK_ / 128), 256, GSMEM_B>>>(
        xh, xl, wqh, wql, q_p, NTOK_, NH_ * QKD_, DIM_);

    // 2. kv = x @ wkv_a^T : (4096, 576), K=2048
    bf3_gemm_mma<<<dim3((KVLORA_ + ROPE_ + 127) / 128, NTOK_ / 128), 256, GSMEM_B>>>(
        xh, xl, wkvah, wkval, kv_p, NTOK_, KVLORA_ + ROPE_, DIM_);

    // 3. RMSNorm kv_c (-> hi/lo) + RoPE k_pe
    kv_post_kernel<<<NTOK_, 128>>>(kv_p, kvnw, fc, fs, kvch, kvcl, kpe_p);

    // 4. kvb = kv_c_norm @ wkv_b^T : (4096, 4096), K=512
    bf3_gemm_mma<<<dim3((NH_ * (NOPE_ + VD_) + 127) / 128, NTOK_ / 128), 256, GSMEM_B>>>(
        kvch, kvcl, wkvbh, wkvbl, kvb_p, NTOK_, NH_ * (NOPE_ + VD_), KVLORA_);

    // 5. attention operand prep
    {
        const int n = B_ * NH_ * S_ * QKD_;
        prep_k<<<(n + 255) / 256, 256>>>(kvb_p, kpe_p, kh, kl);
        prep_vt<<<dim3(S_ / 64, VD_ / 64, B_ * NH_), 256>>>(kvb_p, vth, vtl);
    }

    // 6. tensor-core causal flash attention (-> hi/lo bf16)
    flash_mma<<<dim3(S_ / 64, NH_, B_), 128, FA2_SMEM>>>(
        q_p, kh, kl, vth, vtl, atth, attl, scale);

    // 7. out = attn @ wo^T : (4096, 2048), K=2048
    bf3_gemm_mma<<<dim3((DIM_ + 127) / 128, NTOK_ / 128), 256, GSMEM_B>>>(
        atth, attl, woh, wol, out, NTOK_, DIM_, NH_ * VD_);
}